// round 1
// baseline (speedup 1.0000x reference)
#include <cuda_runtime.h>
#include <math.h>

#define B_   2
#define L_   1024
#define DIN  1024
#define DM   2048
#define DS   16
#define DR   128
#define KCONV 4
#define BL   (B_ * L_)

// ---------------- scratch (device globals: no allocation allowed) ----------------
__device__ float g_x[BL * DM];      // x_in @ W_in
__device__ float g_res[BL * DM];    // x_in @ W_res
__device__ float g_xc[BL * DM];     // silu(conv(x))
__device__ float g_Bp[BL * DS];
__device__ float g_Cp[BL * DS];
__device__ float g_dtr[BL * DR];
__device__ float g_delta[BL * DM];
__device__ float g_y[BL * DM];

// ---------------- big SGEMM: 128x128 tile, BK=8, 8x8 per thread ----------------
// A: MxK row-major, B: KxN row-major, C: MxN row-major.
// Requires M%128==0, N%128==0, K%8==0 (true for all big shapes here).
__global__ __launch_bounds__(256) void sgemm128(
    const float* __restrict__ A, const float* __restrict__ B, float* __restrict__ C,
    int M, int N, int K)
{
    constexpr int BM = 128, BN = 128, BK = 8;
    __shared__ float As[BK][BM];   // transposed A tile
    __shared__ float Bs[BK][BN];

    const int tid = threadIdx.x;
    const int bm = blockIdx.y * BM;
    const int bn = blockIdx.x * BN;
    const int tx = tid & 15;          // 16 col groups
    const int ty = tid >> 4;          // 16 row groups
    const int row0 = ty * 8;
    const int col0 = tx * 8;

    // cooperative loads: 1 float4 per thread per tile
    const int aRow = tid >> 1;            // 0..127
    const int aCol = (tid & 1) << 2;      // 0 or 4
    const int bRow = tid >> 5;            // 0..7
    const int bCol = (tid & 31) << 2;     // 0..124

    const float* Ag = A + (size_t)(bm + aRow) * K + aCol;
    const float* Bg = B + (size_t)bRow * N + bn + bCol;

    float acc[8][8] = {};

    for (int k0 = 0; k0 < K; k0 += BK) {
        float4 av = *(const float4*)(Ag);
        float4 bv = *(const float4*)(Bg);
        As[aCol + 0][aRow] = av.x;
        As[aCol + 1][aRow] = av.y;
        As[aCol + 2][aRow] = av.z;
        As[aCol + 3][aRow] = av.w;
        *(float4*)(&Bs[bRow][bCol]) = bv;
        __syncthreads();

        #pragma unroll
        for (int k = 0; k < BK; k++) {
            float ar[8], br[8];
            float4 a0 = *(const float4*)(&As[k][row0]);
            float4 a1 = *(const float4*)(&As[k][row0 + 4]);
            float4 b0 = *(const float4*)(&Bs[k][col0]);
            float4 b1 = *(const float4*)(&Bs[k][col0 + 4]);
            ar[0]=a0.x; ar[1]=a0.y; ar[2]=a0.z; ar[3]=a0.w;
            ar[4]=a1.x; ar[5]=a1.y; ar[6]=a1.z; ar[7]=a1.w;
            br[0]=b0.x; br[1]=b0.y; br[2]=b0.z; br[3]=b0.w;
            br[4]=b1.x; br[5]=b1.y; br[6]=b1.z; br[7]=b1.w;
            #pragma unroll
            for (int i = 0; i < 8; i++)
                #pragma unroll
                for (int j = 0; j < 8; j++)
                    acc[i][j] = fmaf(ar[i], br[j], acc[i][j]);
        }
        __syncthreads();
        Ag += BK;
        Bg += (size_t)BK * N;
    }

    float* Cp = C + (size_t)(bm + row0) * N + bn + col0;
    #pragma unroll
    for (int i = 0; i < 8; i++) {
        *(float4*)(Cp + (size_t)i * N + 0) =
            make_float4(acc[i][0], acc[i][1], acc[i][2], acc[i][3]);
        *(float4*)(Cp + (size_t)i * N + 4) =
            make_float4(acc[i][4], acc[i][5], acc[i][6], acc[i][7]);
    }
}

// ---------------- skinny SGEMM: 64x32 tile, BK=32, 4x2 per thread ----------------
// For N = 16 / 128 projections. Requires M%64==0, K%32==0; N guarded.
__global__ __launch_bounds__(256) void sgemm_sk(
    const float* __restrict__ A, const float* __restrict__ B, float* __restrict__ C,
    int M, int N, int K)
{
    constexpr int BM = 64, BN = 32, BK = 32;
    __shared__ float As[BK][BM];   // transposed
    __shared__ float Bs[BK][BN];

    const int tid = threadIdx.x;
    const int bm = blockIdx.y * BM;
    const int bn = blockIdx.x * BN;
    const int tx = tid & 15;
    const int ty = tid >> 4;

    float acc[4][2] = {};

    const int aRow = tid >> 2;            // 0..63
    const int aK   = (tid & 3) << 3;      // 0,8,16,24
    const int bK   = tid >> 3;            // 0..31
    const int bCol = (tid & 7) << 2;      // 0..28

    const float* Ag = A + (size_t)(bm + aRow) * K + aK;

    for (int k0 = 0; k0 < K; k0 += BK) {
        float4 a0 = *(const float4*)(Ag + k0);
        float4 a1 = *(const float4*)(Ag + k0 + 4);
        As[aK + 0][aRow] = a0.x; As[aK + 1][aRow] = a0.y;
        As[aK + 2][aRow] = a0.z; As[aK + 3][aRow] = a0.w;
        As[aK + 4][aRow] = a1.x; As[aK + 5][aRow] = a1.y;
        As[aK + 6][aRow] = a1.z; As[aK + 7][aRow] = a1.w;

        const int gr = k0 + bK;
        #pragma unroll
        for (int j = 0; j < 4; j++) {
            const int c = bn + bCol + j;
            Bs[bK][bCol + j] = (c < N) ? B[(size_t)gr * N + c] : 0.0f;
        }
        __syncthreads();

        #pragma unroll
        for (int k = 0; k < BK; k++) {
            float ar[4];
            #pragma unroll
            for (int i = 0; i < 4; i++) ar[i] = As[k][ty * 4 + i];
            const float br0 = Bs[k][tx * 2 + 0];
            const float br1 = Bs[k][tx * 2 + 1];
            #pragma unroll
            for (int i = 0; i < 4; i++) {
                acc[i][0] = fmaf(ar[i], br0, acc[i][0]);
                acc[i][1] = fmaf(ar[i], br1, acc[i][1]);
            }
        }
        __syncthreads();
    }

    #pragma unroll
    for (int i = 0; i < 4; i++) {
        const int r = bm + ty * 4 + i;
        #pragma unroll
        for (int j = 0; j < 2; j++) {
            const int c = bn + tx * 2 + j;
            if (c < N) C[(size_t)r * N + c] = acc[i][j];
        }
    }
}

// ---------------- causal depthwise conv (K=4) + SiLU : g_x -> g_xc ----------------
__global__ void conv_silu_kernel(const float* __restrict__ cw, const float* __restrict__ cb)
{
    const int idx = blockIdx.x * blockDim.x + threadIdx.x;
    if (idx >= BL * DM) return;
    const int d  = idx % DM;
    const int bl = idx / DM;
    const int l  = bl % L_;

    float v = cb[d];
    #pragma unroll
    for (int i = 0; i < KCONV; i++) {
        const int li = l - (KCONV - 1) + i;
        if (li >= 0)
            v = fmaf(g_x[idx + (li - l) * DM], cw[d * KCONV + i], v);
    }
    g_xc[idx] = v / (1.0f + __expf(-v));   // silu
}

// ---------------- bias + softplus on g_delta (in place) ----------------
__global__ void softplus_kernel(const float* __restrict__ dtb)
{
    const int idx = blockIdx.x * blockDim.x + threadIdx.x;
    if (idx >= BL * DM) return;
    const int d = idx % DM;
    const float x = g_delta[idx] + dtb[d];
    g_delta[idx] = (x > 20.0f) ? x : log1pf(__expf(x));
}

// ---------------- selective scan: one 16-lane group per (b,d) ----------------
// Includes +D*xc and *silu(res) epilogues; writes g_y.
__global__ __launch_bounds__(256) void scan_kernel(
    const float* __restrict__ A_log, const float* __restrict__ Dp)
{
    const int gid = blockIdx.x * blockDim.x + threadIdx.x;
    const int p = gid >> 4;          // (b,d) pair
    const int n = gid & 15;          // state index
    if (p >= B_ * DM) return;
    const int b = p / DM;
    const int d = p % DM;

    const float a  = -__expf(A_log[d * DS + n]);
    const float Dd = Dp[d];

    const size_t base  = (size_t)b * L_ * DM + d;
    const size_t baseS = (size_t)b * L_ * DS + n;
    const float* dl  = g_delta + base;
    const float* xcp = g_xc    + base;
    const float* rp  = g_res   + base;
    const float* bp  = g_Bp    + baseS;
    const float* cp  = g_Cp    + baseS;
    float*       yp  = g_y     + base;

    float h = 0.0f;
    for (int l = 0; l < L_; l++) {
        const float dlt = dl[(size_t)l * DM];
        const float xv  = xcp[(size_t)l * DM];
        const float bv  = bp[(size_t)l * DS];
        const float cv  = cp[(size_t)l * DS];

        const float dA = __expf(dlt * a);
        h = fmaf(dA, h, dlt * bv * xv);

        float py = h * cv;
        py += __shfl_xor_sync(0xffffffffu, py, 8);
        py += __shfl_xor_sync(0xffffffffu, py, 4);
        py += __shfl_xor_sync(0xffffffffu, py, 2);
        py += __shfl_xor_sync(0xffffffffu, py, 1);

        if (n == 0) {
            const float rv  = rp[(size_t)l * DM];
            const float sil = rv / (1.0f + __expf(-rv));
            yp[(size_t)l * DM] = (py + Dd * xv) * sil;
        }
    }
}

// ---------------- launch ----------------
extern "C" void kernel_launch(void* const* d_in, const int* in_sizes, int n_in,
                              void* d_out, int out_size)
{
    const float* x_in   = (const float*)d_in[0];
    const float* W_in   = (const float*)d_in[1];
    const float* W_res  = (const float*)d_in[2];
    const float* W_out  = (const float*)d_in[3];
    const float* conv_w = (const float*)d_in[4];
    const float* conv_b = (const float*)d_in[5];
    const float* A_log  = (const float*)d_in[6];
    const float* Dvec   = (const float*)d_in[7];
    const float* W_B    = (const float*)d_in[8];
    const float* W_C    = (const float*)d_in[9];
    const float* W_dt   = (const float*)d_in[10];
    const float* dt_w   = (const float*)d_in[11];
    const float* dt_b   = (const float*)d_in[12];
    float* out = (float*)d_out;

    float *px, *pres, *pxc, *pBp, *pCp, *pdtr, *pdelta, *py;
    cudaGetSymbolAddress((void**)&px,     g_x);
    cudaGetSymbolAddress((void**)&pres,   g_res);
    cudaGetSymbolAddress((void**)&pxc,    g_xc);
    cudaGetSymbolAddress((void**)&pBp,    g_Bp);
    cudaGetSymbolAddress((void**)&pCp,    g_Cp);
    cudaGetSymbolAddress((void**)&pdtr,   g_dtr);
    cudaGetSymbolAddress((void**)&pdelta, g_delta);
    cudaGetSymbolAddress((void**)&py,     g_y);

    // 1) input projections: (BL,DIN)@(DIN,DM)
    sgemm128<<<dim3(DM / 128, BL / 128), 256>>>(x_in, W_in,  px,   BL, DM, DIN);
    sgemm128<<<dim3(DM / 128, BL / 128), 256>>>(x_in, W_res, pres, BL, DM, DIN);

    // 2) causal depthwise conv + silu
    conv_silu_kernel<<<(BL * DM + 255) / 256, 256>>>(conv_w, conv_b);

    // 3) skinny projections from xc
    sgemm_sk<<<dim3(1,        BL / 64), 256>>>(pxc, W_B,  pBp,  BL, DS, DM);
    sgemm_sk<<<dim3(1,        BL / 64), 256>>>(pxc, W_C,  pCp,  BL, DS, DM);
    sgemm_sk<<<dim3(DR / 32,  BL / 64), 256>>>(pxc, W_dt, pdtr, BL, DR, DM);

    // 4) delta = softplus(dtr @ dt_w + dt_b)
    sgemm128<<<dim3(DM / 128, BL / 128), 256>>>(pdtr, dt_w, pdelta, BL, DM, DR);
    softplus_kernel<<<(BL * DM + 255) / 256, 256>>>(dt_b);

    // 5) selective scan (+ D*xc, * silu(res))
    scan_kernel<<<(B_ * DM * 16) / 256, 256>>>(A_log, Dvec);

    // 6) output projection: (BL,DM)@(DM,DIN) -> out
    sgemm128<<<dim3(DIN / 128, BL / 128), 256>>>(py, W_out, out, BL, DIN, DM);
}

// round 3
// speedup vs baseline: 1.7303x; 1.7303x over previous
#include <cuda_runtime.h>
#include <math.h>
#include <stdint.h>

#define B_    2
#define L_    1024
#define DIN   1024
#define DM    2048
#define DS    16
#define DR    128
#define KCONV 4
#define BL    (B_ * L_)
#define NPROJ 160   /* DS + DS + DR fused projection width */

// ---------------- scratch (device globals; no dynamic allocation allowed) ----------------
__device__ float g_xr[BL * DIN];      // tf32-rounded x_in
__device__ float g_x[BL * DM];        // x_in @ W_in
__device__ float g_res[BL * DM];      // silu(x_in @ W_res)
__device__ float g_xc[BL * DM];       // rna(silu(conv(x)))
__device__ float g_proj[BL * NPROJ];  // [Bp | Cp | dtr] (tf32-rounded)
__device__ float g_delta[BL * DM];    // softplus(dtr @ dt_w + b)
__device__ float g_y[BL * DM];        // scan output (tf32-rounded)
__device__ float g_Wt_in[DM * DIN];   // W_in^T
__device__ float g_Wt_res[DM * DIN];
__device__ float g_Wt_out[DIN * DM];
__device__ float g_Wt_cat[NPROJ * DM];  // [W_B^T ; W_C^T ; W_dt^T]
__device__ float g_Wt_dtw[DM * DR];   // dt_w^T

// ---------------- helpers ----------------
__device__ __forceinline__ float rna_tf32(float x) {
    float r; asm("cvt.rna.tf32.f32 %0, %1;" : "=f"(r) : "f"(x)); return r;
}
__device__ __forceinline__ void mma_tf32(float* c, const uint32_t* a, const uint32_t* b) {
    asm volatile(
        "mma.sync.aligned.m16n8k8.row.col.f32.tf32.tf32.f32 "
        "{%0,%1,%2,%3}, {%4,%5,%6,%7}, {%8,%9}, {%0,%1,%2,%3};"
        : "+f"(c[0]), "+f"(c[1]), "+f"(c[2]), "+f"(c[3])
        : "r"(a[0]), "r"(a[1]), "r"(a[2]), "r"(a[3]), "r"(b[0]), "r"(b[1]));
}

// ---------------- tf32 mma.sync GEMM ----------------
// C(M x N) = A(M x K) @ Bt(N x K)^T, all row-major fp32 (values pre-rounded to tf32).
// CTA tile 128x128, BK=16, 256 threads (8 warps, warp tile 64x32).
// EPI: 0=none, 1=silu, 2=softplus(x+bias), 3=round-to-tf32
#define SA 136
template<int EPI>
__global__ void __launch_bounds__(256) gemm_mma(
    const float* __restrict__ A, int lda,
    const float* __restrict__ Bt,
    float* __restrict__ C, int ldc,
    const float* __restrict__ bias,
    int N, int K)
{
    __shared__ float As[2][16][SA];
    __shared__ float Bs[2][16][SA];

    const int tid  = threadIdx.x;
    const int wid  = tid >> 5, lane = tid & 31;
    const int gid  = lane >> 2, tig = lane & 3;
    const int bm   = blockIdx.y * 128, bn = blockIdx.x * 128;
    const int wm   = (wid >> 2) * 64;   // warp row tile (2 rows of warps)
    const int wn   = (wid & 3) * 32;    // warp col tile (4 cols of warps)

    float acc[4][4][4] = {};            // [m-atom][n-atom][frag]

    // cooperative load mapping: each thread loads 2 float4 (8 consecutive k) of one row
    const int lrow = tid >> 1;          // 0..127
    const int lk0  = (tid & 1) * 8;     // k offset 0 or 8

    const float* Ag = A  + (size_t)(bm + lrow) * lda + lk0;
    const float* Bg = Bt + (size_t)(bn + lrow) * K   + lk0;
    const bool  bok = (bn + lrow) < N;

    const float4 f4z = make_float4(0.f, 0.f, 0.f, 0.f);

    // prologue: stage k-chunk 0 into buffer 0
    {
        float4 a0 = *(const float4*)(Ag);
        float4 a1 = *(const float4*)(Ag + 4);
        float4 b0 = bok ? *(const float4*)(Bg)     : f4z;
        float4 b1 = bok ? *(const float4*)(Bg + 4) : f4z;
        As[0][lk0 + 0][lrow] = a0.x; As[0][lk0 + 1][lrow] = a0.y;
        As[0][lk0 + 2][lrow] = a0.z; As[0][lk0 + 3][lrow] = a0.w;
        As[0][lk0 + 4][lrow] = a1.x; As[0][lk0 + 5][lrow] = a1.y;
        As[0][lk0 + 6][lrow] = a1.z; As[0][lk0 + 7][lrow] = a1.w;
        Bs[0][lk0 + 0][lrow] = b0.x; Bs[0][lk0 + 1][lrow] = b0.y;
        Bs[0][lk0 + 2][lrow] = b0.z; Bs[0][lk0 + 3][lrow] = b0.w;
        Bs[0][lk0 + 4][lrow] = b1.x; Bs[0][lk0 + 5][lrow] = b1.y;
        Bs[0][lk0 + 6][lrow] = b1.z; Bs[0][lk0 + 7][lrow] = b1.w;
    }
    __syncthreads();

    const int KT = K >> 4;
    for (int kt = 0; kt < KT; ++kt) {
        const int cur = kt & 1;

        // prefetch next k-chunk into registers
        float4 na0, na1, nb0, nb1;
        if (kt + 1 < KT) {
            const float* Ag2 = Ag + (kt + 1) * 16;
            const float* Bg2 = Bg + (kt + 1) * 16;
            na0 = *(const float4*)(Ag2);
            na1 = *(const float4*)(Ag2 + 4);
            nb0 = bok ? *(const float4*)(Bg2)     : f4z;
            nb1 = bok ? *(const float4*)(Bg2 + 4) : f4z;
        }

        // compute on current buffer: 2 k8 steps
        #pragma unroll
        for (int ks = 0; ks < 2; ++ks) {
            const int kb = ks * 8;
            uint32_t af[4][4], bf[4][2];
            #pragma unroll
            for (int i = 0; i < 4; ++i) {
                const int mr = wm + i * 16;
                af[i][0] = __float_as_uint(As[cur][kb + tig    ][mr + gid    ]);
                af[i][1] = __float_as_uint(As[cur][kb + tig    ][mr + gid + 8]);
                af[i][2] = __float_as_uint(As[cur][kb + tig + 4][mr + gid    ]);
                af[i][3] = __float_as_uint(As[cur][kb + tig + 4][mr + gid + 8]);
            }
            #pragma unroll
            for (int j = 0; j < 4; ++j) {
                const int nc = wn + j * 8;
                bf[j][0] = __float_as_uint(Bs[cur][kb + tig    ][nc + gid]);
                bf[j][1] = __float_as_uint(Bs[cur][kb + tig + 4][nc + gid]);
            }
            #pragma unroll
            for (int i = 0; i < 4; ++i)
                #pragma unroll
                for (int j = 0; j < 4; ++j)
                    mma_tf32(acc[i][j], af[i], bf[j]);
        }

        // stage prefetched chunk into the other buffer
        if (kt + 1 < KT) {
            const int nb = cur ^ 1;
            As[nb][lk0 + 0][lrow] = na0.x; As[nb][lk0 + 1][lrow] = na0.y;
            As[nb][lk0 + 2][lrow] = na0.z; As[nb][lk0 + 3][lrow] = na0.w;
            As[nb][lk0 + 4][lrow] = na1.x; As[nb][lk0 + 5][lrow] = na1.y;
            As[nb][lk0 + 6][lrow] = na1.z; As[nb][lk0 + 7][lrow] = na1.w;
            Bs[nb][lk0 + 0][lrow] = nb0.x; Bs[nb][lk0 + 1][lrow] = nb0.y;
            Bs[nb][lk0 + 2][lrow] = nb0.z; Bs[nb][lk0 + 3][lrow] = nb0.w;
            Bs[nb][lk0 + 4][lrow] = nb1.x; Bs[nb][lk0 + 5][lrow] = nb1.y;
            Bs[nb][lk0 + 6][lrow] = nb1.z; Bs[nb][lk0 + 7][lrow] = nb1.w;
        }
        __syncthreads();
    }

    // epilogue
    #pragma unroll
    for (int i = 0; i < 4; ++i) {
        const int r0 = bm + wm + i * 16 + gid;
        #pragma unroll
        for (int j = 0; j < 4; ++j) {
            const int col = bn + wn + j * 8 + tig * 2;
            if (col < N) {
                float v[4];
                #pragma unroll
                for (int q = 0; q < 4; ++q) v[q] = acc[i][j][q];
                if (EPI == 1) {
                    #pragma unroll
                    for (int q = 0; q < 4; ++q) v[q] = v[q] / (1.0f + __expf(-v[q]));
                } else if (EPI == 2) {
                    const float bb0 = bias[col], bb1 = bias[col + 1];
                    v[0] += bb0; v[1] += bb1; v[2] += bb0; v[3] += bb1;
                    #pragma unroll
                    for (int q = 0; q < 4; ++q)
                        v[q] = (v[q] > 20.0f) ? v[q] : log1pf(__expf(v[q]));
                } else if (EPI == 3) {
                    #pragma unroll
                    for (int q = 0; q < 4; ++q) v[q] = rna_tf32(v[q]);
                }
                *(float2*)(C + (size_t)r0 * ldc + col)       = make_float2(v[0], v[1]);
                *(float2*)(C + (size_t)(r0 + 8) * ldc + col) = make_float2(v[2], v[3]);
            }
        }
    }
}

// ---------------- transpose with tf32 rounding: out[c][r] = rna(in[r][c]) ----------------
__global__ void transpose_rna(const float* __restrict__ in, float* __restrict__ out,
                              int R, int Ccols)
{
    __shared__ float t[32][33];
    const int r0 = blockIdx.y * 32, c0 = blockIdx.x * 32;
    #pragma unroll
    for (int dy = 0; dy < 32; dy += 8) {
        const int r = r0 + threadIdx.y + dy, c = c0 + threadIdx.x;
        if (r < R && c < Ccols) t[threadIdx.y + dy][threadIdx.x] = in[(size_t)r * Ccols + c];
    }
    __syncthreads();
    #pragma unroll
    for (int dy = 0; dy < 32; dy += 8) {
        const int rr = c0 + threadIdx.y + dy, cc = r0 + threadIdx.x;
        if (rr < Ccols && cc < R) out[(size_t)rr * R + cc] = rna_tf32(t[threadIdx.x][threadIdx.y + dy]);
    }
}

// ---------------- elementwise tf32 rounding copy ----------------
__global__ void round_copy(const float* __restrict__ in, float* __restrict__ out, int n)
{
    const int i = blockIdx.x * blockDim.x + threadIdx.x;
    if (i < n) out[i] = rna_tf32(in[i]);
}

// ---------------- causal depthwise conv (K=4) + SiLU + tf32 round : g_x -> g_xc ---------
__global__ void conv_silu_kernel(const float* __restrict__ cw, const float* __restrict__ cb)
{
    const int idx = blockIdx.x * blockDim.x + threadIdx.x;
    if (idx >= BL * DM) return;
    const int d  = idx % DM;
    const int bl = idx / DM;
    const int l  = bl % L_;

    float v = cb[d];
    #pragma unroll
    for (int i = 0; i < KCONV; i++) {
        const int li = l - (KCONV - 1) + i;
        if (li >= 0)
            v = fmaf(g_x[idx + (li - l) * DM], cw[d * KCONV + i], v);
    }
    v = v / (1.0f + __expf(-v));
    g_xc[idx] = rna_tf32(v);
}

// ---------------- selective scan: one 16-lane group per (b,d) ----------------
__global__ __launch_bounds__(256) void scan_kernel(
    const float* __restrict__ A_log, const float* __restrict__ Dp)
{
    const int gid = blockIdx.x * blockDim.x + threadIdx.x;
    const int p = gid >> 4;
    const int n = gid & 15;
    if (p >= B_ * DM) return;
    const int b = p / DM;
    const int d = p % DM;

    const float a  = -__expf(A_log[d * DS + n]);
    const float Dd = Dp[d];

    const size_t base  = (size_t)b * L_ * DM + d;
    const size_t baseS = (size_t)b * L_ * NPROJ;
    const float* dl  = g_delta + base;
    const float* xcp = g_xc    + base;
    const float* rp  = g_res   + base;          // already silu'd
    const float* bp  = g_proj  + baseS + n;
    const float* cp  = g_proj  + baseS + DS + n;
    float*       yp  = g_y     + base;

    float h = 0.0f;
    for (int l = 0; l < L_; l++) {
        const float dlt = dl[(size_t)l * DM];
        const float xv  = xcp[(size_t)l * DM];
        const float bv  = bp[(size_t)l * NPROJ];
        const float cv  = cp[(size_t)l * NPROJ];

        const float dA = __expf(dlt * a);
        h = fmaf(dA, h, dlt * bv * xv);

        float py = h * cv;
        py += __shfl_xor_sync(0xffffffffu, py, 8);
        py += __shfl_xor_sync(0xffffffffu, py, 4);
        py += __shfl_xor_sync(0xffffffffu, py, 2);
        py += __shfl_xor_sync(0xffffffffu, py, 1);

        if (n == 0) {
            const float sil = rp[(size_t)l * DM];
            yp[(size_t)l * DM] = rna_tf32((py + Dd * xv) * sil);
        }
    }
}

// ---------------- launch ----------------
extern "C" void kernel_launch(void* const* d_in, const int* in_sizes, int n_in,
                              void* d_out, int out_size)
{
    const float* x_in   = (const float*)d_in[0];
    const float* W_in   = (const float*)d_in[1];
    const float* W_res  = (const float*)d_in[2];
    const float* W_out  = (const float*)d_in[3];
    const float* conv_w = (const float*)d_in[4];
    const float* conv_b = (const float*)d_in[5];
    const float* A_log  = (const float*)d_in[6];
    const float* Dvec   = (const float*)d_in[7];
    const float* W_B    = (const float*)d_in[8];
    const float* W_C    = (const float*)d_in[9];
    const float* W_dt   = (const float*)d_in[10];
    const float* dt_w   = (const float*)d_in[11];
    const float* dt_b   = (const float*)d_in[12];
    float* out = (float*)d_out;

    float *pxr, *px, *pres, *pxc, *pproj, *pdelta, *py;
    float *pWti, *pWtr, *pWto, *pWtc, *pWtd;
    cudaGetSymbolAddress((void**)&pxr,    g_xr);
    cudaGetSymbolAddress((void**)&px,     g_x);
    cudaGetSymbolAddress((void**)&pres,   g_res);
    cudaGetSymbolAddress((void**)&pxc,    g_xc);
    cudaGetSymbolAddress((void**)&pproj,  g_proj);
    cudaGetSymbolAddress((void**)&pdelta, g_delta);
    cudaGetSymbolAddress((void**)&py,     g_y);
    cudaGetSymbolAddress((void**)&pWti,   g_Wt_in);
    cudaGetSymbolAddress((void**)&pWtr,   g_Wt_res);
    cudaGetSymbolAddress((void**)&pWto,   g_Wt_out);
    cudaGetSymbolAddress((void**)&pWtc,   g_Wt_cat);
    cudaGetSymbolAddress((void**)&pWtd,   g_Wt_dtw);

    dim3 tb(32, 8);
    // weight preprocessing (transpose + tf32 rounding)
    transpose_rna<<<dim3(DM / 32, DIN / 32), tb>>>(W_in,  pWti, DIN, DM);
    transpose_rna<<<dim3(DM / 32, DIN / 32), tb>>>(W_res, pWtr, DIN, DM);
    transpose_rna<<<dim3(DIN / 32, DM / 32), tb>>>(W_out, pWto, DM, DIN);
    transpose_rna<<<dim3(1,        DM / 32), tb>>>(W_B,   pWtc,               DM, DS);
    transpose_rna<<<dim3(1,        DM / 32), tb>>>(W_C,   pWtc + DS * DM,     DM, DS);
    transpose_rna<<<dim3(DR / 32,  DM / 32), tb>>>(W_dt,  pWtc + 2 * DS * DM, DM, DR);
    transpose_rna<<<dim3(DM / 32,  DR / 32), tb>>>(dt_w,  pWtd, DR, DM);
    round_copy<<<(BL * DIN + 255) / 256, 256>>>(x_in, pxr, BL * DIN);

    // 1) input projections (tf32 mma.sync)
    gemm_mma<0><<<dim3(DM / 128, BL / 128), 256>>>(pxr, DIN, pWti, px,   DM, nullptr, DM, DIN);
    gemm_mma<1><<<dim3(DM / 128, BL / 128), 256>>>(pxr, DIN, pWtr, pres, DM, nullptr, DM, DIN);

    // 2) causal conv + silu (+tf32 round)
    conv_silu_kernel<<<(BL * DM + 255) / 256, 256>>>(conv_w, conv_b);

    // 3) fused skinny projections: xc @ [W_B|W_C|W_dt] -> g_proj (tf32-rounded)
    gemm_mma<3><<<dim3(2, BL / 128), 256>>>(pxc, DM, pWtc, pproj, NPROJ, nullptr, NPROJ, DM);

    // 4) delta = softplus(dtr @ dt_w + dt_b), fused epilogue
    gemm_mma<2><<<dim3(DM / 128, BL / 128), 256>>>(pproj + 2 * DS, NPROJ, pWtd, pdelta, DM, dt_b, DM, DR);

    // 5) selective scan (+ D*xc, * silu(res))
    scan_kernel<<<(B_ * DM * 16) / 256, 256>>>(A_log, Dvec);

    // 6) output projection
    gemm_mma<0><<<dim3(DIN / 128, BL / 128), 256>>>(py, DM, pWto, out, DIN, nullptr, DIN, DM);
}

// round 4
// speedup vs baseline: 1.7740x; 1.0252x over previous
#include <cuda_runtime.h>
#include <math.h>
#include <stdint.h>

#define B_    2
#define L_    1024
#define DIN   1024
#define DM    2048
#define DS    16
#define DR    128
#define KCONV 4
#define BL    (B_ * L_)
#define NPROJ 160

// ---------------- scratch ----------------
__device__ float g_xr[BL * DIN];
__device__ float g_x[BL * DM];
__device__ float g_res[BL * DM];        // silu(x_in @ W_res)
__device__ float g_xc[BL * DM];
__device__ float g_proj[BL * NPROJ];    // [Bp | Cp | dtr]
__device__ float g_delta[BL * DM];
__device__ float g_y[BL * DM];
__device__ float g_Wt_inres[2 * DM * DIN];  // [W_in^T ; W_res^T]
__device__ float g_Wt_out[DIN * DM];
__device__ float g_Wt_cat[NPROJ * DM];
__device__ float g_Wt_dtw[DM * DR];

// ---------------- helpers ----------------
__device__ __forceinline__ float rna_tf32(float x) {
    float r; asm("cvt.rna.tf32.f32 %0, %1;" : "=f"(r) : "f"(x)); return r;
}
__device__ __forceinline__ void mma_tf32(float* c, const uint32_t* a, const uint32_t* b) {
    asm volatile(
        "mma.sync.aligned.m16n8k8.row.col.f32.tf32.tf32.f32 "
        "{%0,%1,%2,%3}, {%4,%5,%6,%7}, {%8,%9}, {%0,%1,%2,%3};"
        : "+f"(c[0]), "+f"(c[1]), "+f"(c[2]), "+f"(c[3])
        : "r"(a[0]), "r"(a[1]), "r"(a[2]), "r"(a[3]), "r"(b[0]), "r"(b[1]));
}
__device__ __forceinline__ void cpa16(uint32_t dst, const void* src) {
    asm volatile("cp.async.cg.shared.global [%0], [%1], 16;" :: "r"(dst), "l"(src));
}
__device__ __forceinline__ void cpa_commit() { asm volatile("cp.async.commit_group;"); }
__device__ __forceinline__ void cpa_wait0()  { asm volatile("cp.async.wait_group 0;" ::: "memory"); }

// ============ gemm_big: 128x256 CTA tile, 8 warps (64x64), cp.async staging ============
// C = A(M,K) @ Bt(N,K)^T. Requires N % 256 == 0, K % 16 == 0.
// EPI: 0=none, 2=softplus(+bias), 4=dual: cols<DM -> C plain, cols>=DM -> C2 with silu
#define BST 20   /* smem row stride (floats) for BK=16 tiles; conflict-free for gid/tig pattern */
template<int EPI>
__global__ void __launch_bounds__(256, 1) gemm_big(
    const float* __restrict__ A, int lda,
    const float* __restrict__ Bt,
    float* __restrict__ C, float* __restrict__ C2, int ldc,
    const float* __restrict__ bias, int K)
{
    extern __shared__ float sm[];
    float* As = sm;                    // [2][128][BST]
    float* Bs = sm + 2 * 128 * BST;    // [2][256][BST]

    const int tid  = threadIdx.x;
    const int wid  = tid >> 5, lane = tid & 31;
    const int gid  = lane >> 2, tig = lane & 3;
    const int bm   = blockIdx.y * 128, bn = blockIdx.x * 256;
    const int wm   = (wid >> 2) * 64;
    const int wn   = (wid & 3) * 64;

    float acc[4][8][4] = {};

    const int lrow = tid >> 1;            // 0..127
    const int lk0  = (tid & 1) * 8;       // 0 or 8

    const float* Ag  = A  + (size_t)(bm + lrow) * lda + lk0;
    const float* Bg0 = Bt + (size_t)(bn + lrow) * K + lk0;
    const float* Bg1 = Bt + (size_t)(bn + lrow + 128) * K + lk0;

    uint32_t sA = (uint32_t)__cvta_generic_to_shared(As);
    uint32_t sB = (uint32_t)__cvta_generic_to_shared(Bs);
    const uint32_t dA = sA + (uint32_t)(lrow * BST + lk0) * 4;
    const uint32_t dB0 = sB + (uint32_t)(lrow * BST + lk0) * 4;
    const uint32_t dB1 = sB + (uint32_t)((lrow + 128) * BST + lk0) * 4;
    const uint32_t bufA = 128 * BST * 4, bufB = 256 * BST * 4;

    const int NC = K >> 4;

    // prologue: chunk 0 -> buffer 0
    cpa16(dA,      Ag);       cpa16(dA + 16,      Ag + 4);
    cpa16(dB0,     Bg0);      cpa16(dB0 + 16,     Bg0 + 4);
    cpa16(dB1,     Bg1);      cpa16(dB1 + 16,     Bg1 + 4);
    cpa_commit(); cpa_wait0();
    __syncthreads();

    for (int c = 0; c < NC; ++c) {
        const int cur = c & 1;
        if (c + 1 < NC) {
            const int nb = cur ^ 1;
            const int ko = (c + 1) * 16;
            cpa16(dA + nb * bufA,       Ag + ko);
            cpa16(dA + nb * bufA + 16,  Ag + ko + 4);
            cpa16(dB0 + nb * bufB,      Bg0 + ko);
            cpa16(dB0 + nb * bufB + 16, Bg0 + ko + 4);
            cpa16(dB1 + nb * bufB,      Bg1 + ko);
            cpa16(dB1 + nb * bufB + 16, Bg1 + ko + 4);
            cpa_commit();
        }
        const float* Ab = As + cur * 128 * BST;
        const float* Bb = Bs + cur * 256 * BST;
        #pragma unroll
        for (int ks = 0; ks < 2; ++ks) {
            const int kb = ks * 8;
            uint32_t af[4][4], bf[8][2];
            #pragma unroll
            for (int i = 0; i < 4; ++i) {
                const int mr = wm + i * 16;
                af[i][0] = __float_as_uint(Ab[(mr + gid    ) * BST + kb + tig    ]);
                af[i][1] = __float_as_uint(Ab[(mr + gid + 8) * BST + kb + tig    ]);
                af[i][2] = __float_as_uint(Ab[(mr + gid    ) * BST + kb + tig + 4]);
                af[i][3] = __float_as_uint(Ab[(mr + gid + 8) * BST + kb + tig + 4]);
            }
            #pragma unroll
            for (int j = 0; j < 8; ++j) {
                const int nc = wn + j * 8;
                bf[j][0] = __float_as_uint(Bb[(nc + gid) * BST + kb + tig    ]);
                bf[j][1] = __float_as_uint(Bb[(nc + gid) * BST + kb + tig + 4]);
            }
            #pragma unroll
            for (int i = 0; i < 4; ++i)
                #pragma unroll
                for (int j = 0; j < 8; ++j)
                    mma_tf32(acc[i][j], af[i], bf[j]);
        }
        cpa_wait0();
        __syncthreads();
    }

    // epilogue
    #pragma unroll
    for (int i = 0; i < 4; ++i) {
        const int r0 = bm + wm + i * 16 + gid;
        #pragma unroll
        for (int j = 0; j < 8; ++j) {
            const int col = bn + wn + j * 8 + tig * 2;
            float v[4];
            #pragma unroll
            for (int q = 0; q < 4; ++q) v[q] = acc[i][j][q];
            float* dst;
            int cc = col;
            if (EPI == 2) {
                const float bb0 = bias[col], bb1 = bias[col + 1];
                v[0] += bb0; v[1] += bb1; v[2] += bb0; v[3] += bb1;
                #pragma unroll
                for (int q = 0; q < 4; ++q)
                    v[q] = (v[q] > 20.0f) ? v[q] : log1pf(__expf(v[q]));
                dst = C;
            } else if (EPI == 4) {
                if (col < DM) { dst = C; }
                else {
                    cc = col - DM; dst = C2;
                    #pragma unroll
                    for (int q = 0; q < 4; ++q) v[q] = v[q] / (1.0f + __expf(-v[q]));
                }
            } else {
                dst = C;
            }
            *(float2*)(dst + (size_t)r0 * ldc + cc)       = make_float2(v[0], v[1]);
            *(float2*)(dst + (size_t)(r0 + 8) * ldc + cc) = make_float2(v[2], v[3]);
        }
    }
}

// ============ gemm_mma (128x128, proven): for N=160 proj and out-proj ============
#define SA 136
template<int EPI>   // 0=none, 3=round-to-tf32
__global__ void __launch_bounds__(256) gemm_mma(
    const float* __restrict__ A, int lda,
    const float* __restrict__ Bt,
    float* __restrict__ C, int ldc,
    int N, int K)
{
    __shared__ float As[2][16][SA];
    __shared__ float Bs[2][16][SA];

    const int tid  = threadIdx.x;
    const int wid  = tid >> 5, lane = tid & 31;
    const int gid  = lane >> 2, tig = lane & 3;
    const int bm   = blockIdx.y * 128, bn = blockIdx.x * 128;
    const int wm   = (wid >> 2) * 64;
    const int wn   = (wid & 3) * 32;

    float acc[4][4][4] = {};

    const int lrow = tid >> 1;
    const int lk0  = (tid & 1) * 8;

    const float* Ag = A  + (size_t)(bm + lrow) * lda + lk0;
    const float* Bg = Bt + (size_t)(bn + lrow) * K   + lk0;
    const bool  bok = (bn + lrow) < N;
    const float4 f4z = make_float4(0.f, 0.f, 0.f, 0.f);

    {
        float4 a0 = *(const float4*)(Ag);
        float4 a1 = *(const float4*)(Ag + 4);
        float4 b0 = bok ? *(const float4*)(Bg)     : f4z;
        float4 b1 = bok ? *(const float4*)(Bg + 4) : f4z;
        As[0][lk0 + 0][lrow] = a0.x; As[0][lk0 + 1][lrow] = a0.y;
        As[0][lk0 + 2][lrow] = a0.z; As[0][lk0 + 3][lrow] = a0.w;
        As[0][lk0 + 4][lrow] = a1.x; As[0][lk0 + 5][lrow] = a1.y;
        As[0][lk0 + 6][lrow] = a1.z; As[0][lk0 + 7][lrow] = a1.w;
        Bs[0][lk0 + 0][lrow] = b0.x; Bs[0][lk0 + 1][lrow] = b0.y;
        Bs[0][lk0 + 2][lrow] = b0.z; Bs[0][lk0 + 3][lrow] = b0.w;
        Bs[0][lk0 + 4][lrow] = b1.x; Bs[0][lk0 + 5][lrow] = b1.y;
        Bs[0][lk0 + 6][lrow] = b1.z; Bs[0][lk0 + 7][lrow] = b1.w;
    }
    __syncthreads();

    const int KT = K >> 4;
    for (int kt = 0; kt < KT; ++kt) {
        const int cur = kt & 1;
        float4 na0, na1, nb0, nb1;
        if (kt + 1 < KT) {
            const float* Ag2 = Ag + (kt + 1) * 16;
            const float* Bg2 = Bg + (kt + 1) * 16;
            na0 = *(const float4*)(Ag2);
            na1 = *(const float4*)(Ag2 + 4);
            nb0 = bok ? *(const float4*)(Bg2)     : f4z;
            nb1 = bok ? *(const float4*)(Bg2 + 4) : f4z;
        }
        #pragma unroll
        for (int ks = 0; ks < 2; ++ks) {
            const int kb = ks * 8;
            uint32_t af[4][4], bf[4][2];
            #pragma unroll
            for (int i = 0; i < 4; ++i) {
                const int mr = wm + i * 16;
                af[i][0] = __float_as_uint(As[cur][kb + tig    ][mr + gid    ]);
                af[i][1] = __float_as_uint(As[cur][kb + tig    ][mr + gid + 8]);
                af[i][2] = __float_as_uint(As[cur][kb + tig + 4][mr + gid    ]);
                af[i][3] = __float_as_uint(As[cur][kb + tig + 4][mr + gid + 8]);
            }
            #pragma unroll
            for (int j = 0; j < 4; ++j) {
                const int nc = wn + j * 8;
                bf[j][0] = __float_as_uint(Bs[cur][kb + tig    ][nc + gid]);
                bf[j][1] = __float_as_uint(Bs[cur][kb + tig + 4][nc + gid]);
            }
            #pragma unroll
            for (int i = 0; i < 4; ++i)
                #pragma unroll
                for (int j = 0; j < 4; ++j)
                    mma_tf32(acc[i][j], af[i], bf[j]);
        }
        if (kt + 1 < KT) {
            const int nb = cur ^ 1;
            As[nb][lk0 + 0][lrow] = na0.x; As[nb][lk0 + 1][lrow] = na0.y;
            As[nb][lk0 + 2][lrow] = na0.z; As[nb][lk0 + 3][lrow] = na0.w;
            As[nb][lk0 + 4][lrow] = na1.x; As[nb][lk0 + 5][lrow] = na1.y;
            As[nb][lk0 + 6][lrow] = na1.z; As[nb][lk0 + 7][lrow] = na1.w;
            Bs[nb][lk0 + 0][lrow] = nb0.x; Bs[nb][lk0 + 1][lrow] = nb0.y;
            Bs[nb][lk0 + 2][lrow] = nb0.z; Bs[nb][lk0 + 3][lrow] = nb0.w;
            Bs[nb][lk0 + 4][lrow] = nb1.x; Bs[nb][lk0 + 5][lrow] = nb1.y;
            Bs[nb][lk0 + 6][lrow] = nb1.z; Bs[nb][lk0 + 7][lrow] = nb1.w;
        }
        __syncthreads();
    }

    #pragma unroll
    for (int i = 0; i < 4; ++i) {
        const int r0 = bm + wm + i * 16 + gid;
        #pragma unroll
        for (int j = 0; j < 4; ++j) {
            const int col = bn + wn + j * 8 + tig * 2;
            if (col < N) {
                float v[4];
                #pragma unroll
                for (int q = 0; q < 4; ++q) v[q] = acc[i][j][q];
                if (EPI == 3) {
                    #pragma unroll
                    for (int q = 0; q < 4; ++q) v[q] = rna_tf32(v[q]);
                }
                *(float2*)(C + (size_t)r0 * ldc + col)       = make_float2(v[0], v[1]);
                *(float2*)(C + (size_t)(r0 + 8) * ldc + col) = make_float2(v[2], v[3]);
            }
        }
    }
}

// ---------------- transpose with tf32 rounding ----------------
__global__ void transpose_rna(const float* __restrict__ in, float* __restrict__ out,
                              int R, int Ccols)
{
    __shared__ float t[32][33];
    const int r0 = blockIdx.y * 32, c0 = blockIdx.x * 32;
    #pragma unroll
    for (int dy = 0; dy < 32; dy += 8) {
        const int r = r0 + threadIdx.y + dy, c = c0 + threadIdx.x;
        if (r < R && c < Ccols) t[threadIdx.y + dy][threadIdx.x] = in[(size_t)r * Ccols + c];
    }
    __syncthreads();
    #pragma unroll
    for (int dy = 0; dy < 32; dy += 8) {
        const int rr = c0 + threadIdx.y + dy, cc = r0 + threadIdx.x;
        if (rr < Ccols && cc < R) out[(size_t)rr * R + cc] = rna_tf32(t[threadIdx.x][threadIdx.y + dy]);
    }
}

__global__ void round_copy(const float* __restrict__ in, float* __restrict__ out, int n)
{
    const int i = blockIdx.x * blockDim.x + threadIdx.x;
    if (i < n) out[i] = rna_tf32(in[i]);
}

// ---------------- causal depthwise conv + SiLU + tf32 round ----------------
__global__ void conv_silu_kernel(const float* __restrict__ cw, const float* __restrict__ cb)
{
    const int idx = blockIdx.x * blockDim.x + threadIdx.x;
    if (idx >= BL * DM) return;
    const int d  = idx % DM;
    const int bl = idx / DM;
    const int l  = bl % L_;

    float v = cb[d];
    #pragma unroll
    for (int i = 0; i < KCONV; i++) {
        const int li = l - (KCONV - 1) + i;
        if (li >= 0)
            v = fmaf(g_x[idx + (li - l) * DM], cw[d * KCONV + i], v);
    }
    v = v / (1.0f + __expf(-v));
    g_xc[idx] = rna_tf32(v);
}

// ---------------- selective scan: smem-tiled, cp.async double-buffered ----------------
// CTA: 256 threads = 16 groups x 16 lanes; group g -> (b, d0+g); lane = state n.
#define ST 64   /* timesteps per tile */
__global__ __launch_bounds__(256) void scan_kernel(
    const float* __restrict__ A_log, const float* __restrict__ Dp)
{
    __shared__ float sd[2][ST][16];
    __shared__ float sx[2][ST][16];
    __shared__ float sr[2][ST][16];
    __shared__ float sp[2][ST][32];
    __shared__ float sy[ST][16];

    const int tid = threadIdx.x;
    const int g = tid >> 4, n = tid & 15;
    const int b  = blockIdx.x / (DM / 16);
    const int d0 = (blockIdx.x % (DM / 16)) * 16;
    const int d  = d0 + g;

    const float a  = -__expf(A_log[d * DS + n]);
    const float Dd = Dp[d];

    const float* baseD = g_delta + (size_t)b * L_ * DM + d0;
    const float* baseX = g_xc    + (size_t)b * L_ * DM + d0;
    const float* baseR = g_res   + (size_t)b * L_ * DM + d0;
    const float* baseP = g_proj  + (size_t)b * L_ * NPROJ;
    float*       baseY = g_y     + (size_t)b * L_ * DM + d0;

    // cp.async dest addresses
    const int t4 = tid >> 2, q4 = tid & 3;     // 16-wide tiles: row t4, quad q4
    const int t8 = tid >> 3, q8 = tid & 7;     // 32-wide tile (proj): 2 reps

    uint32_t aD = (uint32_t)__cvta_generic_to_shared(&sd[0][t4][q4 * 4]);
    uint32_t aX = (uint32_t)__cvta_generic_to_shared(&sx[0][t4][q4 * 4]);
    uint32_t aR = (uint32_t)__cvta_generic_to_shared(&sr[0][t4][q4 * 4]);
    uint32_t aP0 = (uint32_t)__cvta_generic_to_shared(&sp[0][t8][q8 * 4]);
    uint32_t aP1 = (uint32_t)__cvta_generic_to_shared(&sp[0][t8 + 32][q8 * 4]);
    const uint32_t bD = sizeof(float) * ST * 16;
    const uint32_t bP = sizeof(float) * ST * 32;

    auto stage = [&](int l0, int buf) {
        cpa16(aD + buf * bD, baseD + (size_t)(l0 + t4) * DM + q4 * 4);
        cpa16(aX + buf * bD, baseX + (size_t)(l0 + t4) * DM + q4 * 4);
        cpa16(aR + buf * bD, baseR + (size_t)(l0 + t4) * DM + q4 * 4);
        cpa16(aP0 + buf * bP, baseP + (size_t)(l0 + t8) * NPROJ + q8 * 4);
        cpa16(aP1 + buf * bP, baseP + (size_t)(l0 + t8 + 32) * NPROJ + q8 * 4);
        cpa_commit();
    };

    stage(0, 0);
    cpa_wait0();
    __syncthreads();

    float h = 0.0f;
    const int NT = L_ / ST;
    for (int tt = 0; tt < NT; ++tt) {
        const int buf = tt & 1;
        if (tt + 1 < NT) stage((tt + 1) * ST, buf ^ 1);

        #pragma unroll 4
        for (int t = 0; t < ST; ++t) {
            const float dlt = sd[buf][t][g];
            const float xv  = sx[buf][t][g];
            const float bv  = sp[buf][t][n];
            const float cv  = sp[buf][t][16 + n];

            const float dA = __expf(dlt * a);
            h = fmaf(dA, h, dlt * bv * xv);

            float py = h * cv;
            py += __shfl_xor_sync(0xffffffffu, py, 8);
            py += __shfl_xor_sync(0xffffffffu, py, 4);
            py += __shfl_xor_sync(0xffffffffu, py, 2);
            py += __shfl_xor_sync(0xffffffffu, py, 1);

            if (n == 0) {
                const float sil = sr[buf][t][g];
                sy[t][g] = rna_tf32((py + Dd * xv) * sil);
            }
        }
        cpa_wait0();
        __syncthreads();
        // flush y tile (coalesced)
        {
            float4 v = *(float4*)(&sy[t4][q4 * 4]);
            *(float4*)(baseY + (size_t)(tt * ST + t4) * DM + q4 * 4) = v;
        }
        __syncthreads();
    }
}

// ---------------- launch ----------------
extern "C" void kernel_launch(void* const* d_in, const int* in_sizes, int n_in,
                              void* d_out, int out_size)
{
    const float* x_in   = (const float*)d_in[0];
    const float* W_in   = (const float*)d_in[1];
    const float* W_res  = (const float*)d_in[2];
    const float* W_out  = (const float*)d_in[3];
    const float* conv_w = (const float*)d_in[4];
    const float* conv_b = (const float*)d_in[5];
    const float* A_log  = (const float*)d_in[6];
    const float* Dvec   = (const float*)d_in[7];
    const float* W_B    = (const float*)d_in[8];
    const float* W_C    = (const float*)d_in[9];
    const float* W_dt   = (const float*)d_in[10];
    const float* dt_w   = (const float*)d_in[11];
    const float* dt_b   = (const float*)d_in[12];
    float* out = (float*)d_out;

    float *pxr, *px, *pres, *pxc, *pproj, *pdelta, *py;
    float *pWir, *pWto, *pWtc, *pWtd;
    cudaGetSymbolAddress((void**)&pxr,    g_xr);
    cudaGetSymbolAddress((void**)&px,     g_x);
    cudaGetSymbolAddress((void**)&pres,   g_res);
    cudaGetSymbolAddress((void**)&pxc,    g_xc);
    cudaGetSymbolAddress((void**)&pproj,  g_proj);
    cudaGetSymbolAddress((void**)&pdelta, g_delta);
    cudaGetSymbolAddress((void**)&py,     g_y);
    cudaGetSymbolAddress((void**)&pWir,   g_Wt_inres);
    cudaGetSymbolAddress((void**)&pWto,   g_Wt_out);
    cudaGetSymbolAddress((void**)&pWtc,   g_Wt_cat);
    cudaGetSymbolAddress((void**)&pWtd,   g_Wt_dtw);

    const int smem_big = 2 * (128 + 256) * BST * 4;
    cudaFuncSetAttribute(gemm_big<4>, cudaFuncAttributeMaxDynamicSharedMemorySize, smem_big);
    cudaFuncSetAttribute(gemm_big<2>, cudaFuncAttributeMaxDynamicSharedMemorySize, smem_big);

    dim3 tb(32, 8);
    transpose_rna<<<dim3(DM / 32, DIN / 32), tb>>>(W_in,  pWir,            DIN, DM);
    transpose_rna<<<dim3(DM / 32, DIN / 32), tb>>>(W_res, pWir + DM * DIN, DIN, DM);
    transpose_rna<<<dim3(DIN / 32, DM / 32), tb>>>(W_out, pWto, DM, DIN);
    transpose_rna<<<dim3(1,        DM / 32), tb>>>(W_B,   pWtc,               DM, DS);
    transpose_rna<<<dim3(1,        DM / 32), tb>>>(W_C,   pWtc + DS * DM,     DM, DS);
    transpose_rna<<<dim3(DR / 32,  DM / 32), tb>>>(W_dt,  pWtc + 2 * DS * DM, DM, DR);
    transpose_rna<<<dim3(DM / 32,  DR / 32), tb>>>(dt_w,  pWtd, DR, DM);
    round_copy<<<(BL * DIN + 255) / 256, 256>>>(x_in, pxr, BL * DIN);

    // 1) fused in+res projection: N=4096, dual-output epilogue
    gemm_big<4><<<dim3(2 * DM / 256, BL / 128), 256, smem_big>>>(
        pxr, DIN, pWir, px, pres, DM, nullptr, DIN);

    // 2) conv + silu
    conv_silu_kernel<<<(BL * DM + 255) / 256, 256>>>(conv_w, conv_b);

    // 3) fused skinny projections (N=160)
    gemm_mma<3><<<dim3(2, BL / 128), 256>>>(pxc, DM, pWtc, pproj, NPROJ, NPROJ, DM);

    // 4) delta = softplus(dtr @ dt_w + dt_b)
    gemm_big<2><<<dim3(DM / 256, BL / 128), 256, smem_big>>>(
        pproj + 2 * DS, NPROJ, pWtd, pdelta, nullptr, DM, dt_b, DR);

    // 5) selective scan (smem-tiled)
    scan_kernel<<<B_ * DM / 16, 256>>>(A_log, Dvec);

    // 6) output projection
    gemm_mma<0><<<dim3(DIN / 128, BL / 128), 256>>>(py, DM, pWto, out, DIN, DIN, DM);
}

// round 5
// speedup vs baseline: 4.1589x; 2.3444x over previous
#include <cuda_runtime.h>
#include <cuda_fp16.h>
#include <math.h>
#include <stdint.h>

#define B_    2
#define L_    1024
#define DIN   1024
#define DM    2048
#define DS    16
#define DR    128
#define KCONV 4
#define BL    (B_ * L_)
#define NPROJ 160

// ---------------- scratch ----------------
__device__ __half g_xh[BL * DIN];          // fp16 x_in
__device__ float  g_x[BL * DM];            // x_in @ W_in (fp32, conv input)
__device__ float  g_res[BL * DM];          // silu(x_in @ W_res)
__device__ float  g_xc[BL * DM];           // silu(conv(x)) fp32 (scan)
__device__ __half g_xch[BL * DM];          // fp16 copy (GEMM A)
__device__ float  g_proj[BL * NPROJ];      // [Bp | Cp | dtr] fp32 (scan)
__device__ __half g_projh[BL * NPROJ];     // fp16 copy (delta GEMM A)
__device__ float  g_delta[BL * DM];
__device__ __half g_yh[BL * DM];           // scan output fp16 (out-proj A)
__device__ __half g_Wth_inres[2 * DM * DIN];
__device__ __half g_Wth_out[DIN * DM];
__device__ __half g_Wth_cat[NPROJ * DM];
__device__ __half g_Wth_dtw[DM * DR];

// ---------------- helpers ----------------
__device__ __forceinline__ void mma_f16(float* c, const uint32_t* a, const uint32_t* b) {
    asm volatile(
        "mma.sync.aligned.m16n8k16.row.col.f32.f16.f16.f32 "
        "{%0,%1,%2,%3}, {%4,%5,%6,%7}, {%8,%9}, {%0,%1,%2,%3};"
        : "+f"(c[0]), "+f"(c[1]), "+f"(c[2]), "+f"(c[3])
        : "r"(a[0]), "r"(a[1]), "r"(a[2]), "r"(a[3]), "r"(b[0]), "r"(b[1]));
}
__device__ __forceinline__ void cpa16(uint32_t dst, const void* src) {
    asm volatile("cp.async.cg.shared.global [%0], [%1], 16;" :: "r"(dst), "l"(src));
}
__device__ __forceinline__ void cpa16z(uint32_t dst, const void* src, int srcbytes) {
    asm volatile("cp.async.cg.shared.global [%0], [%1], 16, %2;"
                 :: "r"(dst), "l"(src), "r"(srcbytes));
}
__device__ __forceinline__ void cpa_commit() { asm volatile("cp.async.commit_group;"); }
__device__ __forceinline__ void cpa_wait0()  { asm volatile("cp.async.wait_group 0;" ::: "memory"); }

// ============ fp16 mma GEMM ============
// C(M x N) = A(M x K) @ Bt(N x K)^T. A, Bt fp16; accum/output fp32.
// NB: number of 128-row B blocks (N-tile = NB*128). BK = 32 halfs.
// EPI: 0=none, 2=softplus(+bias), 3=dual fp32 C + fp16 H, 4=dual: col<DM->C, else C2 silu
#define SH 40   /* smem row stride in halfs (32 + 8 pad): conflict-free for frag loads */
template<int NB, int EPI>
__global__ void __launch_bounds__(256, 1) gemm_h(
    const __half* __restrict__ A, int lda,
    const __half* __restrict__ Bt,
    float* __restrict__ C, float* __restrict__ C2, __half* __restrict__ H, int ldc,
    const float* __restrict__ bias, int N, int K)
{
    extern __shared__ __half sh[];
    __half* As = sh;                       // [2][128][SH]
    __half* Bs = sh + 2 * 128 * SH;        // [2][NB*128][SH]
    constexpr int NROWS = NB * 128;
    constexpr int NATOM = NB * 4;

    const int tid  = threadIdx.x;
    const int wid  = tid >> 5, lane = tid & 31;
    const int gid  = lane >> 2, tig = lane & 3;
    const int bm   = blockIdx.y * 128, bn = blockIdx.x * NROWS;
    const int wm   = (wid >> 2) * 64;
    const int wn   = (wid & 3) * (NB * 16 * 2);   // NB=2:64, NB=1:32

    float acc[4][NATOM][4] = {};

    const int lrow = tid >> 1;            // 0..127
    const int lk0  = (tid & 1) * 16;      // half-offset 0 or 16

    const __half* Ag = A + (size_t)(bm + lrow) * lda + lk0;

    uint32_t sA = (uint32_t)__cvta_generic_to_shared(As);
    uint32_t sB = (uint32_t)__cvta_generic_to_shared(Bs);
    const uint32_t dA = sA + (uint32_t)(lrow * SH + lk0) * 2;
    const uint32_t bufA = 128 * SH * 2, bufB = NROWS * SH * 2;

    const __half* Bg[NB];
    uint32_t dB[NB];
    int bbytes[NB];
    #pragma unroll
    for (int r = 0; r < NB; ++r) {
        const int brow = bn + lrow + 128 * r;
        Bg[r] = Bt + (size_t)brow * K + lk0;
        dB[r] = sB + (uint32_t)((lrow + 128 * r) * SH + lk0) * 2;
        bbytes[r] = (brow < N) ? 16 : 0;
    }

    const int NC = K >> 5;

    // prologue: chunk 0 -> buffer 0
    cpa16(dA, Ag); cpa16(dA + 16, Ag + 8);
    #pragma unroll
    for (int r = 0; r < NB; ++r) {
        cpa16z(dB[r],      Bg[r],     bbytes[r]);
        cpa16z(dB[r] + 16, Bg[r] + 8, bbytes[r]);
    }
    cpa_commit(); cpa_wait0();
    __syncthreads();

    for (int c = 0; c < NC; ++c) {
        const int cur = c & 1;
        if (c + 1 < NC) {
            const int nb2 = cur ^ 1;
            const int ko = (c + 1) * 32;
            cpa16(dA + nb2 * bufA,      Ag + ko);
            cpa16(dA + nb2 * bufA + 16, Ag + ko + 8);
            #pragma unroll
            for (int r = 0; r < NB; ++r) {
                cpa16z(dB[r] + nb2 * bufB,      Bg[r] + ko,     bbytes[r]);
                cpa16z(dB[r] + nb2 * bufB + 16, Bg[r] + ko + 8, bbytes[r]);
            }
            cpa_commit();
        }
        const __half* Ab = As + cur * 128 * SH;
        const __half* Bb = Bs + cur * NROWS * SH;
        #pragma unroll
        for (int ks = 0; ks < 2; ++ks) {
            const int kb = ks * 16;
            uint32_t af[4][4], bf[NATOM][2];
            #pragma unroll
            for (int i = 0; i < 4; ++i) {
                const int mr = wm + i * 16;
                af[i][0] = *(const uint32_t*)&Ab[(mr + gid    ) * SH + kb + 2 * tig    ];
                af[i][1] = *(const uint32_t*)&Ab[(mr + gid + 8) * SH + kb + 2 * tig    ];
                af[i][2] = *(const uint32_t*)&Ab[(mr + gid    ) * SH + kb + 2 * tig + 8];
                af[i][3] = *(const uint32_t*)&Ab[(mr + gid + 8) * SH + kb + 2 * tig + 8];
            }
            #pragma unroll
            for (int j = 0; j < NATOM; ++j) {
                const int nc = wn + j * 8;
                bf[j][0] = *(const uint32_t*)&Bb[(nc + gid) * SH + kb + 2 * tig    ];
                bf[j][1] = *(const uint32_t*)&Bb[(nc + gid) * SH + kb + 2 * tig + 8];
            }
            #pragma unroll
            for (int i = 0; i < 4; ++i)
                #pragma unroll
                for (int j = 0; j < NATOM; ++j)
                    mma_f16(acc[i][j], af[i], bf[j]);
        }
        cpa_wait0();
        __syncthreads();
    }

    // epilogue
    #pragma unroll
    for (int i = 0; i < 4; ++i) {
        const int r0 = bm + wm + i * 16 + gid;
        #pragma unroll
        for (int j = 0; j < NATOM; ++j) {
            const int col = bn + wn + j * 8 + tig * 2;
            if (col >= N) continue;
            float v[4];
            #pragma unroll
            for (int q = 0; q < 4; ++q) v[q] = acc[i][j][q];
            if (EPI == 2) {
                const float bb0 = bias[col], bb1 = bias[col + 1];
                v[0] += bb0; v[1] += bb1; v[2] += bb0; v[3] += bb1;
                #pragma unroll
                for (int q = 0; q < 4; ++q)
                    v[q] = (v[q] > 20.0f) ? v[q] : log1pf(__expf(v[q]));
                *(float2*)(C + (size_t)r0 * ldc + col)       = make_float2(v[0], v[1]);
                *(float2*)(C + (size_t)(r0 + 8) * ldc + col) = make_float2(v[2], v[3]);
            } else if (EPI == 3) {
                *(float2*)(C + (size_t)r0 * ldc + col)       = make_float2(v[0], v[1]);
                *(float2*)(C + (size_t)(r0 + 8) * ldc + col) = make_float2(v[2], v[3]);
                *(__half2*)(H + (size_t)r0 * ldc + col)       = __floats2half2_rn(v[0], v[1]);
                *(__half2*)(H + (size_t)(r0 + 8) * ldc + col) = __floats2half2_rn(v[2], v[3]);
            } else if (EPI == 4) {
                if (col < DM) {
                    *(float2*)(C + (size_t)r0 * ldc + col)       = make_float2(v[0], v[1]);
                    *(float2*)(C + (size_t)(r0 + 8) * ldc + col) = make_float2(v[2], v[3]);
                } else {
                    #pragma unroll
                    for (int q = 0; q < 4; ++q) v[q] = v[q] / (1.0f + __expf(-v[q]));
                    const int cc = col - DM;
                    *(float2*)(C2 + (size_t)r0 * ldc + cc)       = make_float2(v[0], v[1]);
                    *(float2*)(C2 + (size_t)(r0 + 8) * ldc + cc) = make_float2(v[2], v[3]);
                }
            } else {
                *(float2*)(C + (size_t)r0 * ldc + col)       = make_float2(v[0], v[1]);
                *(float2*)(C + (size_t)(r0 + 8) * ldc + col) = make_float2(v[2], v[3]);
            }
        }
    }
}

// ---------------- transpose fp32 -> fp16: out[c][r] = h(in[r][c]) ----------------
__global__ void transpose_h(const float* __restrict__ in, __half* __restrict__ out,
                            int R, int Ccols)
{
    __shared__ float t[32][33];
    const int r0 = blockIdx.y * 32, c0 = blockIdx.x * 32;
    #pragma unroll
    for (int dy = 0; dy < 32; dy += 8) {
        const int r = r0 + threadIdx.y + dy, c = c0 + threadIdx.x;
        if (r < R && c < Ccols) t[threadIdx.y + dy][threadIdx.x] = in[(size_t)r * Ccols + c];
    }
    __syncthreads();
    #pragma unroll
    for (int dy = 0; dy < 32; dy += 8) {
        const int rr = c0 + threadIdx.y + dy, cc = r0 + threadIdx.x;
        if (rr < Ccols && cc < R)
            out[(size_t)rr * R + cc] = __float2half(t[threadIdx.x][threadIdx.y + dy]);
    }
}

// ---------------- combined small transposes (W_B, W_C, W_dt, dt_w) ----------------
__global__ void transpose_small(const float* __restrict__ WB, const float* __restrict__ WC,
                                const float* __restrict__ Wdt, const float* __restrict__ dtw,
                                __half* __restrict__ cat, __half* __restrict__ dtwT)
{
    __shared__ float t[32][33];
    const float* in; __half* out; int R, Ccols, rb, cb;
    switch (blockIdx.z) {
        case 0: if (blockIdx.x) return;
                in = WB;  out = cat;               R = DM; Ccols = DS; rb = blockIdx.y; cb = 0; break;
        case 1: if (blockIdx.x) return;
                in = WC;  out = cat + DS * DM;     R = DM; Ccols = DS; rb = blockIdx.y; cb = 0; break;
        case 2: in = Wdt; out = cat + 2 * DS * DM; R = DM; Ccols = DR; rb = blockIdx.y; cb = blockIdx.x; break;
        default:in = dtw; out = dtwT;              R = DR; Ccols = DM; rb = blockIdx.x; cb = blockIdx.y; break;
    }
    const int r0 = rb * 32, c0 = cb * 32;
    #pragma unroll
    for (int dy = 0; dy < 32; dy += 8) {
        const int r = r0 + threadIdx.y + dy, c = c0 + threadIdx.x;
        if (r < R && c < Ccols) t[threadIdx.y + dy][threadIdx.x] = in[(size_t)r * Ccols + c];
    }
    __syncthreads();
    #pragma unroll
    for (int dy = 0; dy < 32; dy += 8) {
        const int rr = c0 + threadIdx.y + dy, cc = r0 + threadIdx.x;
        if (rr < Ccols && cc < R)
            out[(size_t)rr * R + cc] = __float2half(t[threadIdx.x][threadIdx.y + dy]);
    }
}

// ---------------- x_in -> fp16 ----------------
__global__ void cvt_x(const float* __restrict__ in, int n)
{
    const int i = blockIdx.x * blockDim.x + threadIdx.x;
    if (i < n) g_xh[i] = __float2half(in[i]);
}

// ---------------- causal depthwise conv + SiLU ----------------
__global__ void conv_silu_kernel(const float* __restrict__ cw, const float* __restrict__ cb)
{
    const int idx = blockIdx.x * blockDim.x + threadIdx.x;
    if (idx >= BL * DM) return;
    const int d  = idx % DM;
    const int bl = idx / DM;
    const int l  = bl % L_;

    float v = cb[d];
    #pragma unroll
    for (int i = 0; i < KCONV; i++) {
        const int li = l - (KCONV - 1) + i;
        if (li >= 0)
            v = fmaf(g_x[idx + (li - l) * DM], cw[d * KCONV + i], v);
    }
    v = v / (1.0f + __expf(-v));
    g_xc[idx]  = v;
    g_xch[idx] = __float2half(v);
}

// ---------------- selective scan: smem-tiled, cp.async double-buffered ----------------
#define ST 64
__global__ __launch_bounds__(256) void scan_kernel(
    const float* __restrict__ A_log, const float* __restrict__ Dp)
{
    __shared__ float  sd[2][ST][16];
    __shared__ float  sx[2][ST][16];
    __shared__ float  sr[2][ST][16];
    __shared__ float  sp[2][ST][32];
    __shared__ __half sy[ST][16];

    const int tid = threadIdx.x;
    const int g = tid >> 4, n = tid & 15;
    const int b  = blockIdx.x / (DM / 16);
    const int d0 = (blockIdx.x % (DM / 16)) * 16;
    const int d  = d0 + g;

    const float a  = -__expf(A_log[d * DS + n]);
    const float Dd = Dp[d];

    const float* baseD = g_delta + (size_t)b * L_ * DM + d0;
    const float* baseX = g_xc    + (size_t)b * L_ * DM + d0;
    const float* baseR = g_res   + (size_t)b * L_ * DM + d0;
    const float* baseP = g_proj  + (size_t)b * L_ * NPROJ;
    __half*      baseY = g_yh    + (size_t)b * L_ * DM + d0;

    const int t4 = tid >> 2, q4 = tid & 3;
    const int t8 = tid >> 3, q8 = tid & 7;

    uint32_t aD = (uint32_t)__cvta_generic_to_shared(&sd[0][t4][q4 * 4]);
    uint32_t aX = (uint32_t)__cvta_generic_to_shared(&sx[0][t4][q4 * 4]);
    uint32_t aR = (uint32_t)__cvta_generic_to_shared(&sr[0][t4][q4 * 4]);
    uint32_t aP0 = (uint32_t)__cvta_generic_to_shared(&sp[0][t8][q8 * 4]);
    uint32_t aP1 = (uint32_t)__cvta_generic_to_shared(&sp[0][t8 + 32][q8 * 4]);
    const uint32_t bD = sizeof(float) * ST * 16;
    const uint32_t bP = sizeof(float) * ST * 32;

    auto stage = [&](int l0, int buf) {
        cpa16(aD + buf * bD, baseD + (size_t)(l0 + t4) * DM + q4 * 4);
        cpa16(aX + buf * bD, baseX + (size_t)(l0 + t4) * DM + q4 * 4);
        cpa16(aR + buf * bD, baseR + (size_t)(l0 + t4) * DM + q4 * 4);
        cpa16(aP0 + buf * bP, baseP + (size_t)(l0 + t8) * NPROJ + q8 * 4);
        cpa16(aP1 + buf * bP, baseP + (size_t)(l0 + t8 + 32) * NPROJ + q8 * 4);
        cpa_commit();
    };

    stage(0, 0);
    cpa_wait0();
    __syncthreads();

    float h = 0.0f;
    const int NT = L_ / ST;
    for (int tt = 0; tt < NT; ++tt) {
        const int buf = tt & 1;
        if (tt + 1 < NT) stage((tt + 1) * ST, buf ^ 1);

        #pragma unroll 4
        for (int t = 0; t < ST; ++t) {
            const float dlt = sd[buf][t][g];
            const float xv  = sx[buf][t][g];
            const float bv  = sp[buf][t][n];
            const float cv  = sp[buf][t][16 + n];

            const float dA = __expf(dlt * a);
            h = fmaf(dA, h, dlt * bv * xv);

            float py = h * cv;
            py += __shfl_xor_sync(0xffffffffu, py, 8);
            py += __shfl_xor_sync(0xffffffffu, py, 4);
            py += __shfl_xor_sync(0xffffffffu, py, 2);
            py += __shfl_xor_sync(0xffffffffu, py, 1);

            if (n == 0) {
                const float sil = sr[buf][t][g];
                sy[t][g] = __float2half((py + Dd * xv) * sil);
            }
        }
        cpa_wait0();
        __syncthreads();
        if (tid < 128) {
            const int row = tid >> 1, q = tid & 1;
            float4 v = *(float4*)(&sy[row][q * 8]);
            *(float4*)(baseY + (size_t)(tt * ST + row) * DM + q * 8) = v;
        }
        __syncthreads();
    }
}

// ---------------- launch ----------------
extern "C" void kernel_launch(void* const* d_in, const int* in_sizes, int n_in,
                              void* d_out, int out_size)
{
    const float* x_in   = (const float*)d_in[0];
    const float* W_in   = (const float*)d_in[1];
    const float* W_res  = (const float*)d_in[2];
    const float* W_out  = (const float*)d_in[3];
    const float* conv_w = (const float*)d_in[4];
    const float* conv_b = (const float*)d_in[5];
    const float* A_log  = (const float*)d_in[6];
    const float* Dvec   = (const float*)d_in[7];
    const float* W_B    = (const float*)d_in[8];
    const float* W_C    = (const float*)d_in[9];
    const float* W_dt   = (const float*)d_in[10];
    const float* dt_w   = (const float*)d_in[11];
    const float* dt_b   = (const float*)d_in[12];
    float* out = (float*)d_out;

    float  *px, *pres, *pxc, *pproj, *pdelta;
    __half *pxh, *pxch, *pprojh, *pyh, *pWir, *pWto, *pWtc, *pWtd;
    cudaGetSymbolAddress((void**)&px,     g_x);
    cudaGetSymbolAddress((void**)&pres,   g_res);
    cudaGetSymbolAddress((void**)&pxc,    g_xc);
    cudaGetSymbolAddress((void**)&pproj,  g_proj);
    cudaGetSymbolAddress((void**)&pdelta, g_delta);
    cudaGetSymbolAddress((void**)&pxh,    g_xh);
    cudaGetSymbolAddress((void**)&pxch,   g_xch);
    cudaGetSymbolAddress((void**)&pprojh, g_projh);
    cudaGetSymbolAddress((void**)&pyh,    g_yh);
    cudaGetSymbolAddress((void**)&pWir,   g_Wth_inres);
    cudaGetSymbolAddress((void**)&pWto,   g_Wth_out);
    cudaGetSymbolAddress((void**)&pWtc,   g_Wth_cat);
    cudaGetSymbolAddress((void**)&pWtd,   g_Wth_dtw);

    const int smem2 = (2 * 128 + 2 * 256) * SH * 2;  // NB=2
    const int smem1 = (2 * 128 + 2 * 128) * SH * 2;  // NB=1
    cudaFuncSetAttribute(gemm_h<2, 4>, cudaFuncAttributeMaxDynamicSharedMemorySize, smem2);
    cudaFuncSetAttribute(gemm_h<2, 2>, cudaFuncAttributeMaxDynamicSharedMemorySize, smem2);
    cudaFuncSetAttribute(gemm_h<2, 0>, cudaFuncAttributeMaxDynamicSharedMemorySize, smem2);
    cudaFuncSetAttribute(gemm_h<1, 3>, cudaFuncAttributeMaxDynamicSharedMemorySize, smem1);

    dim3 tb(32, 8);
    // 5 prep launches (so ncu -s 5 captures the big GEMM)
    transpose_h<<<dim3(DM / 32, DIN / 32), tb>>>(W_in,  pWir,            DIN, DM);   // 0
    transpose_h<<<dim3(DM / 32, DIN / 32), tb>>>(W_res, pWir + DM * DIN, DIN, DM);   // 1
    transpose_h<<<dim3(DIN / 32, DM / 32), tb>>>(W_out, pWto, DM, DIN);              // 2
    transpose_small<<<dim3(4, 64, 4), tb>>>(W_B, W_C, W_dt, dt_w, pWtc, pWtd);       // 3
    cvt_x<<<(BL * DIN + 255) / 256, 256>>>(x_in, BL * DIN);                          // 4

    // 5: fused in+res projection (N=4096), dual epilogue
    gemm_h<2, 4><<<dim3(16, 16), 256, smem2>>>(
        pxh, DIN, pWir, px, pres, nullptr, DM, nullptr, 2 * DM, DIN);

    // 6: conv + silu
    conv_silu_kernel<<<(BL * DM + 255) / 256, 256>>>(conv_w, conv_b);

    // 7: fused skinny projections (N=160), fp32 + fp16 outputs
    gemm_h<1, 3><<<dim3(2, 16), 256, smem1>>>(
        pxch, DM, pWtc, pproj, nullptr, pprojh, NPROJ, nullptr, NPROJ, DM);

    // 8: delta = softplus(dtr @ dt_w + dt_b)
    gemm_h<2, 2><<<dim3(8, 16), 256, smem2>>>(
        pprojh + 2 * DS, NPROJ, pWtd, pdelta, nullptr, nullptr, DM, dt_b, DM, DR);

    // 9: selective scan
    scan_kernel<<<B_ * DM / 16, 256>>>(A_log, Dvec);

    // 10: output projection (N=1024)
    gemm_h<2, 0><<<dim3(4, 16), 256, smem2>>>(
        pyh, DM, pWto, out, nullptr, nullptr, DIN, nullptr, DIN, DM);
}

// round 6
// speedup vs baseline: 4.8308x; 1.1616x over previous
#include <cuda_runtime.h>
#include <cuda_fp16.h>
#include <math.h>
#include <stdint.h>

#define B_    2
#define L_    1024
#define DIN   1024
#define DM    2048
#define DS    16
#define DR    128
#define KCONV 4
#define BL    (B_ * L_)
#define NPROJ 160

// ---------------- scratch ----------------
__device__ __half g_xh[BL * DIN];
__device__ float  g_x[BL * DM];
__device__ float  g_res[BL * DM];
__device__ float  g_xc[BL * DM];
__device__ __half g_xch[BL * DM];
__device__ float  g_proj[BL * NPROJ];
__device__ __half g_projh[BL * NPROJ];
__device__ float  g_delta[BL * DM];
__device__ __half g_yh[BL * DM];
__device__ __half g_Wth_inres[2 * DM * DIN];
__device__ __half g_Wth_out[DIN * DM];
__device__ __half g_Wth_cat[NPROJ * DM];
__device__ __half g_Wth_dtw[DM * DR];

// ---------------- helpers ----------------
__device__ __forceinline__ void mma_f16(float* c, const uint32_t* a, const uint32_t* b) {
    asm volatile(
        "mma.sync.aligned.m16n8k16.row.col.f32.f16.f16.f32 "
        "{%0,%1,%2,%3}, {%4,%5,%6,%7}, {%8,%9}, {%0,%1,%2,%3};"
        : "+f"(c[0]), "+f"(c[1]), "+f"(c[2]), "+f"(c[3])
        : "r"(a[0]), "r"(a[1]), "r"(a[2]), "r"(a[3]), "r"(b[0]), "r"(b[1]));
}
__device__ __forceinline__ void ldmx4(uint32_t* r, uint32_t addr) {
    asm volatile("ldmatrix.sync.aligned.m8n8.x4.shared.b16 {%0,%1,%2,%3}, [%4];"
        : "=r"(r[0]), "=r"(r[1]), "=r"(r[2]), "=r"(r[3]) : "r"(addr));
}
__device__ __forceinline__ void cpa16(uint32_t dst, const void* src) {
    asm volatile("cp.async.cg.shared.global [%0], [%1], 16;" :: "r"(dst), "l"(src));
}
__device__ __forceinline__ void cpa16z(uint32_t dst, const void* src, int srcbytes) {
    asm volatile("cp.async.cg.shared.global [%0], [%1], 16, %2;"
                 :: "r"(dst), "l"(src), "r"(srcbytes));
}
__device__ __forceinline__ void cpa_commit() { asm volatile("cp.async.commit_group;"); }
__device__ __forceinline__ void cpa_wait1()  { asm volatile("cp.async.wait_group 1;" ::: "memory"); }

// ============ fp16 mma GEMM with ldmatrix + 3-stage cp.async pipeline ============
// C(M x N) = A(M x K) @ Bt(N x K)^T. CTA tile 128 x (NB*128), BK=32, 8 warps.
// SMEM rows: 64B (32 halfs) with quad swizzle q ^ ((row&7)>>1).
// EPI: 0=none, 2=softplus(+bias), 3=dual fp32 C + fp16 H, 4=dual: col<DM->C, else C2 silu
template<int NB, int EPI>
__global__ void __launch_bounds__(256, 1) gemm_h(
    const __half* __restrict__ A, int lda,
    const __half* __restrict__ Bt,
    float* __restrict__ C, float* __restrict__ C2, __half* __restrict__ H, int ldc,
    const float* __restrict__ bias, int N, int K)
{
    constexpr int NROWS = NB * 128;
    constexpr int NATOM = NB * 4;
    constexpr int ABUF  = 128 * 64;       // bytes per A stage
    constexpr int BBUF  = NROWS * 64;     // bytes per B stage
    extern __shared__ char sh[];
    const uint32_t sA = (uint32_t)__cvta_generic_to_shared(sh);
    const uint32_t sB = sA + 3 * ABUF;

    const int tid  = threadIdx.x;
    const int wid  = tid >> 5, lane = tid & 31;
    const int gid  = lane >> 2, tig = lane & 3;
    const int bm   = blockIdx.y * 128, bn = blockIdx.x * NROWS;
    const int wm   = (wid >> 2) * 64;
    const int wn   = (wid & 3) * (NB * 32);

    float acc[4][NATOM][4] = {};

    // ---- cp.async staging mapping: thread -> (row = tid>>1, quads lq, lq+1) ----
    const int lrow = tid >> 1;
    const int lq   = (tid & 1) * 2;
    const int swr  = (lrow & 7) >> 1;
    const uint32_t dA0 = sA + (uint32_t)(lrow * 64 + (((lq    ) ^ swr) << 4));
    const uint32_t dA1 = sA + (uint32_t)(lrow * 64 + (((lq + 1) ^ swr) << 4));
    const __half* Ag = A + (size_t)(bm + lrow) * lda + lq * 8;

    const __half* Bg[NB];
    uint32_t dB0[NB], dB1[NB];
    int bbytes[NB];
    #pragma unroll
    for (int r = 0; r < NB; ++r) {
        const int brow = bn + lrow + 128 * r;
        Bg[r] = Bt + (size_t)brow * K + lq * 8;
        dB0[r] = sB + (uint32_t)((lrow + 128 * r) * 64 + (((lq    ) ^ swr) << 4));
        dB1[r] = sB + (uint32_t)((lrow + 128 * r) * 64 + (((lq + 1) ^ swr) << 4));
        bbytes[r] = (brow < N) ? 16 : 0;
    }

    const int NC = K >> 5;

    auto issue = [&](int c) {
        const int buf = c % 3;
        const int ko  = c * 32;
        cpa16(dA0 + buf * ABUF, Ag + ko);
        cpa16(dA1 + buf * ABUF, Ag + ko + 8);
        #pragma unroll
        for (int r = 0; r < NB; ++r) {
            cpa16z(dB0[r] + buf * BBUF, Bg[r] + ko,     bbytes[r]);
            cpa16z(dB1[r] + buf * BBUF, Bg[r] + ko + 8, bbytes[r]);
        }
        cpa_commit();
    };

    // ---- ldmatrix per-lane address constants ----
    const int swl = (lane & 7) >> 1;
    const uint32_t aLm = sA + (uint32_t)((wm + (lane & 15)) * 64);
    const int aQ = lane >> 4;                      // 0 or 1
    const uint32_t bLm = sB + (uint32_t)((wn + (lane & 7) + ((lane >> 4) & 1) * 8) * 64);
    const int bQ = (lane >> 3) & 1;

    // prologue: stages 0, 1
    issue(0);
    issue(1);

    for (int c = 0; c < NC; ++c) {
        cpa_wait1();            // chunk c arrived (<=1 group pending)
        __syncthreads();        // all warps done with chunk c-1 and see chunk c
        if (c + 2 < NC) issue(c + 2);

        const int buf = c % 3;
        const uint32_t Ab = aLm + buf * ABUF;
        const uint32_t Bb = bLm + buf * BBUF;
        #pragma unroll
        for (int ks = 0; ks < 2; ++ks) {
            uint32_t af[4][4], bf[NATOM][2];
            const uint32_t qa = (uint32_t)(((aQ + 2 * ks) ^ swl) << 4);
            const uint32_t qb = (uint32_t)(((bQ + 2 * ks) ^ swl) << 4);
            #pragma unroll
            for (int i = 0; i < 4; ++i)
                ldmx4(af[i], Ab + i * 1024 + qa);
            #pragma unroll
            for (int jj = 0; jj < NATOM / 2; ++jj)
                ldmx4(&bf[2 * jj][0], Bb + jj * 1024 + qb);
            #pragma unroll
            for (int i = 0; i < 4; ++i)
                #pragma unroll
                for (int j = 0; j < NATOM; ++j)
                    mma_f16(acc[i][j], af[i], bf[j]);
        }
    }

    __syncthreads();

    // ---- epilogue ----
    #pragma unroll
    for (int i = 0; i < 4; ++i) {
        const int r0 = bm + wm + i * 16 + gid;
        #pragma unroll
        for (int j = 0; j < NATOM; ++j) {
            const int col = bn + wn + j * 8 + tig * 2;
            if (col >= N) continue;
            float v[4];
            #pragma unroll
            for (int q = 0; q < 4; ++q) v[q] = acc[i][j][q];
            if (EPI == 2) {
                const float bb0 = bias[col], bb1 = bias[col + 1];
                v[0] += bb0; v[1] += bb1; v[2] += bb0; v[3] += bb1;
                #pragma unroll
                for (int q = 0; q < 4; ++q)
                    v[q] = (v[q] > 20.0f) ? v[q] : log1pf(__expf(v[q]));
                *(float2*)(C + (size_t)r0 * ldc + col)       = make_float2(v[0], v[1]);
                *(float2*)(C + (size_t)(r0 + 8) * ldc + col) = make_float2(v[2], v[3]);
            } else if (EPI == 3) {
                *(float2*)(C + (size_t)r0 * ldc + col)       = make_float2(v[0], v[1]);
                *(float2*)(C + (size_t)(r0 + 8) * ldc + col) = make_float2(v[2], v[3]);
                *(__half2*)(H + (size_t)r0 * ldc + col)       = __floats2half2_rn(v[0], v[1]);
                *(__half2*)(H + (size_t)(r0 + 8) * ldc + col) = __floats2half2_rn(v[2], v[3]);
            } else if (EPI == 4) {
                if (col < DM) {
                    *(float2*)(C + (size_t)r0 * ldc + col)       = make_float2(v[0], v[1]);
                    *(float2*)(C + (size_t)(r0 + 8) * ldc + col) = make_float2(v[2], v[3]);
                } else {
                    #pragma unroll
                    for (int q = 0; q < 4; ++q) v[q] = v[q] / (1.0f + __expf(-v[q]));
                    const int cc = col - DM;
                    *(float2*)(C2 + (size_t)r0 * ldc + cc)       = make_float2(v[0], v[1]);
                    *(float2*)(C2 + (size_t)(r0 + 8) * ldc + cc) = make_float2(v[2], v[3]);
                }
            } else {
                *(float2*)(C + (size_t)r0 * ldc + col)       = make_float2(v[0], v[1]);
                *(float2*)(C + (size_t)(r0 + 8) * ldc + col) = make_float2(v[2], v[3]);
            }
        }
    }
}

// ---------------- transpose fp32 -> fp16 ----------------
__global__ void transpose_h(const float* __restrict__ in, __half* __restrict__ out,
                            int R, int Ccols)
{
    __shared__ float t[32][33];
    const int r0 = blockIdx.y * 32, c0 = blockIdx.x * 32;
    #pragma unroll
    for (int dy = 0; dy < 32; dy += 8) {
        const int r = r0 + threadIdx.y + dy, c = c0 + threadIdx.x;
        if (r < R && c < Ccols) t[threadIdx.y + dy][threadIdx.x] = in[(size_t)r * Ccols + c];
    }
    __syncthreads();
    #pragma unroll
    for (int dy = 0; dy < 32; dy += 8) {
        const int rr = c0 + threadIdx.y + dy, cc = r0 + threadIdx.x;
        if (rr < Ccols && cc < R)
            out[(size_t)rr * R + cc] = __float2half(t[threadIdx.x][threadIdx.y + dy]);
    }
}

// ---------------- combined small transposes ----------------
__global__ void transpose_small(const float* __restrict__ WB, const float* __restrict__ WC,
                                const float* __restrict__ Wdt, const float* __restrict__ dtw,
                                __half* __restrict__ cat, __half* __restrict__ dtwT)
{
    __shared__ float t[32][33];
    const float* in; __half* out; int R, Ccols, rb, cb;
    switch (blockIdx.z) {
        case 0: if (blockIdx.x) return;
                in = WB;  out = cat;               R = DM; Ccols = DS; rb = blockIdx.y; cb = 0; break;
        case 1: if (blockIdx.x) return;
                in = WC;  out = cat + DS * DM;     R = DM; Ccols = DS; rb = blockIdx.y; cb = 0; break;
        case 2: in = Wdt; out = cat + 2 * DS * DM; R = DM; Ccols = DR; rb = blockIdx.y; cb = blockIdx.x; break;
        default:in = dtw; out = dtwT;              R = DR; Ccols = DM; rb = blockIdx.x; cb = blockIdx.y; break;
    }
    const int r0 = rb * 32, c0 = cb * 32;
    #pragma unroll
    for (int dy = 0; dy < 32; dy += 8) {
        const int r = r0 + threadIdx.y + dy, c = c0 + threadIdx.x;
        if (r < R && c < Ccols) t[threadIdx.y + dy][threadIdx.x] = in[(size_t)r * Ccols + c];
    }
    __syncthreads();
    #pragma unroll
    for (int dy = 0; dy < 32; dy += 8) {
        const int rr = c0 + threadIdx.y + dy, cc = r0 + threadIdx.x;
        if (rr < Ccols && cc < R)
            out[(size_t)rr * R + cc] = __float2half(t[threadIdx.x][threadIdx.y + dy]);
    }
}

__global__ void cvt_x(const float* __restrict__ in, int n)
{
    const int i = blockIdx.x * blockDim.x + threadIdx.x;
    if (i < n) g_xh[i] = __float2half(in[i]);
}

// ---------------- causal depthwise conv + SiLU ----------------
__global__ void conv_silu_kernel(const float* __restrict__ cw, const float* __restrict__ cb)
{
    const int idx = blockIdx.x * blockDim.x + threadIdx.x;
    if (idx >= BL * DM) return;
    const int d  = idx % DM;
    const int bl = idx / DM;
    const int l  = bl % L_;

    float v = cb[d];
    #pragma unroll
    for (int i = 0; i < KCONV; i++) {
        const int li = l - (KCONV - 1) + i;
        if (li >= 0)
            v = fmaf(g_x[idx + (li - l) * DM], cw[d * KCONV + i], v);
    }
    v = v / (1.0f + __expf(-v));
    g_xc[idx]  = v;
    g_xch[idx] = __float2half(v);
}

// ---------------- selective scan: smem-tiled, cp.async double-buffered ----------------
__device__ __forceinline__ void cpa_commit2() { asm volatile("cp.async.commit_group;"); }
__device__ __forceinline__ void cpa_wait0()   { asm volatile("cp.async.wait_group 0;" ::: "memory"); }
#define ST 64
__global__ __launch_bounds__(256) void scan_kernel(
    const float* __restrict__ A_log, const float* __restrict__ Dp)
{
    __shared__ float  sd[2][ST][16];
    __shared__ float  sx[2][ST][16];
    __shared__ float  sr[2][ST][16];
    __shared__ float  sp[2][ST][32];
    __shared__ __half sy[ST][16];

    const int tid = threadIdx.x;
    const int g = tid >> 4, n = tid & 15;
    const int b  = blockIdx.x / (DM / 16);
    const int d0 = (blockIdx.x % (DM / 16)) * 16;
    const int d  = d0 + g;

    const float a  = -__expf(A_log[d * DS + n]);
    const float Dd = Dp[d];

    const float* baseD = g_delta + (size_t)b * L_ * DM + d0;
    const float* baseX = g_xc    + (size_t)b * L_ * DM + d0;
    const float* baseR = g_res   + (size_t)b * L_ * DM + d0;
    const float* baseP = g_proj  + (size_t)b * L_ * NPROJ;
    __half*      baseY = g_yh    + (size_t)b * L_ * DM + d0;

    const int t4 = tid >> 2, q4 = tid & 3;
    const int t8 = tid >> 3, q8 = tid & 7;

    uint32_t aD = (uint32_t)__cvta_generic_to_shared(&sd[0][t4][q4 * 4]);
    uint32_t aX = (uint32_t)__cvta_generic_to_shared(&sx[0][t4][q4 * 4]);
    uint32_t aR = (uint32_t)__cvta_generic_to_shared(&sr[0][t4][q4 * 4]);
    uint32_t aP0 = (uint32_t)__cvta_generic_to_shared(&sp[0][t8][q8 * 4]);
    uint32_t aP1 = (uint32_t)__cvta_generic_to_shared(&sp[0][t8 + 32][q8 * 4]);
    const uint32_t bD = sizeof(float) * ST * 16;
    const uint32_t bP = sizeof(float) * ST * 32;

    auto stage = [&](int l0, int buf) {
        cpa16(aD + buf * bD, baseD + (size_t)(l0 + t4) * DM + q4 * 4);
        cpa16(aX + buf * bD, baseX + (size_t)(l0 + t4) * DM + q4 * 4);
        cpa16(aR + buf * bD, baseR + (size_t)(l0 + t4) * DM + q4 * 4);
        cpa16(aP0 + buf * bP, baseP + (size_t)(l0 + t8) * NPROJ + q8 * 4);
        cpa16(aP1 + buf * bP, baseP + (size_t)(l0 + t8 + 32) * NPROJ + q8 * 4);
        cpa_commit2();
    };

    stage(0, 0);
    cpa_wait0();
    __syncthreads();

    float h = 0.0f;
    const int NT = L_ / ST;
    for (int tt = 0; tt < NT; ++tt) {
        const int buf = tt & 1;
        if (tt + 1 < NT) stage((tt + 1) * ST, buf ^ 1);

        #pragma unroll 4
        for (int t = 0; t < ST; ++t) {
            const float dlt = sd[buf][t][g];
            const float xv  = sx[buf][t][g];
            const float bv  = sp[buf][t][n];
            const float cv  = sp[buf][t][16 + n];

            const float dA = __expf(dlt * a);
            h = fmaf(dA, h, dlt * bv * xv);

            float py = h * cv;
            py += __shfl_xor_sync(0xffffffffu, py, 8);
            py += __shfl_xor_sync(0xffffffffu, py, 4);
            py += __shfl_xor_sync(0xffffffffu, py, 2);
            py += __shfl_xor_sync(0xffffffffu, py, 1);

            if (n == 0) {
                const float sil = sr[buf][t][g];
                sy[t][g] = __float2half((py + Dd * xv) * sil);
            }
        }
        cpa_wait0();
        __syncthreads();
        if (tid < 128) {
            const int row = tid >> 1, q = tid & 1;
            float4 v = *(float4*)(&sy[row][q * 8]);
            *(float4*)(baseY + (size_t)(tt * ST + row) * DM + q * 8) = v;
        }
        __syncthreads();
    }
}

// ---------------- launch ----------------
extern "C" void kernel_launch(void* const* d_in, const int* in_sizes, int n_in,
                              void* d_out, int out_size)
{
    const float* x_in   = (const float*)d_in[0];
    const float* W_in   = (const float*)d_in[1];
    const float* W_res  = (const float*)d_in[2];
    const float* W_out  = (const float*)d_in[3];
    const float* conv_w = (const float*)d_in[4];
    const float* conv_b = (const float*)d_in[5];
    const float* A_log  = (const float*)d_in[6];
    const float* Dvec   = (const float*)d_in[7];
    const float* W_B    = (const float*)d_in[8];
    const float* W_C    = (const float*)d_in[9];
    const float* W_dt   = (const float*)d_in[10];
    const float* dt_w   = (const float*)d_in[11];
    const float* dt_b   = (const float*)d_in[12];
    float* out = (float*)d_out;

    float  *px, *pres, *pxc, *pproj, *pdelta;
    __half *pxh, *pxch, *pprojh, *pyh, *pWir, *pWto, *pWtc, *pWtd;
    cudaGetSymbolAddress((void**)&px,     g_x);
    cudaGetSymbolAddress((void**)&pres,   g_res);
    cudaGetSymbolAddress((void**)&pxc,    g_xc);
    cudaGetSymbolAddress((void**)&pproj,  g_proj);
    cudaGetSymbolAddress((void**)&pdelta, g_delta);
    cudaGetSymbolAddress((void**)&pxh,    g_xh);
    cudaGetSymbolAddress((void**)&pxch,   g_xch);
    cudaGetSymbolAddress((void**)&pprojh, g_projh);
    cudaGetSymbolAddress((void**)&pyh,    g_yh);
    cudaGetSymbolAddress((void**)&pWir,   g_Wth_inres);
    cudaGetSymbolAddress((void**)&pWto,   g_Wth_out);
    cudaGetSymbolAddress((void**)&pWtc,   g_Wth_cat);
    cudaGetSymbolAddress((void**)&pWtd,   g_Wth_dtw);

    const int smem2 = 3 * (128 * 64 + 256 * 64);  // NB=2: 73728
    const int smem1 = 3 * (128 * 64 + 128 * 64);  // NB=1: 49152
    cudaFuncSetAttribute(gemm_h<2, 4>, cudaFuncAttributeMaxDynamicSharedMemorySize, smem2);
    cudaFuncSetAttribute(gemm_h<2, 2>, cudaFuncAttributeMaxDynamicSharedMemorySize, smem2);
    cudaFuncSetAttribute(gemm_h<1, 0>, cudaFuncAttributeMaxDynamicSharedMemorySize, smem1);
    cudaFuncSetAttribute(gemm_h<1, 3>, cudaFuncAttributeMaxDynamicSharedMemorySize, smem1);

    dim3 tb(32, 8);
    transpose_h<<<dim3(DM / 32, DIN / 32), tb>>>(W_in,  pWir,            DIN, DM);
    transpose_h<<<dim3(DM / 32, DIN / 32), tb>>>(W_res, pWir + DM * DIN, DIN, DM);
    transpose_h<<<dim3(DIN / 32, DM / 32), tb>>>(W_out, pWto, DM, DIN);
    transpose_small<<<dim3(4, 64, 4), tb>>>(W_B, W_C, W_dt, dt_w, pWtc, pWtd);
    cvt_x<<<(BL * DIN + 255) / 256, 256>>>(x_in, BL * DIN);

    // fused in+res projection (N=4096)
    gemm_h<2, 4><<<dim3(16, 16), 256, smem2>>>(
        pxh, DIN, pWir, px, pres, nullptr, DM, nullptr, 2 * DM, DIN);

    // conv + silu
    conv_silu_kernel<<<(BL * DM + 255) / 256, 256>>>(conv_w, conv_b);

    // fused skinny projections (N=160)
    gemm_h<1, 3><<<dim3(2, 16), 256, smem1>>>(
        pxch, DM, pWtc, pproj, nullptr, pprojh, NPROJ, nullptr, NPROJ, DM);

    // delta = softplus(dtr @ dt_w + dt_b)
    gemm_h<2, 2><<<dim3(8, 16), 256, smem2>>>(
        pprojh + 2 * DS, NPROJ, pWtd, pdelta, nullptr, nullptr, DM, dt_b, DM, DR);

    // selective scan
    scan_kernel<<<B_ * DM / 16, 256>>>(A_log, Dvec);

    // output projection (N=1024, NB=1 -> 128 CTAs)
    gemm_h<1, 0><<<dim3(8, 16), 256, smem1>>>(
        pyh, DM, pWto, out, nullptr, nullptr, DIN, nullptr, DIN, DM);
}

// round 7
// speedup vs baseline: 5.6628x; 1.1722x over previous
#include <cuda_runtime.h>
#include <cuda_fp16.h>
#include <math.h>
#include <stdint.h>

#define B_    2
#define L_    1024
#define DIN   1024
#define DM    2048
#define DS    16
#define DR    128
#define KCONV 4
#define BL    (B_ * L_)
#define NPROJ 160
#define KSPLIT 4

// ---------------- scratch ----------------
__device__ __half g_xh[BL * DIN];
__device__ float  g_x[BL * DM];
__device__ float  g_res[BL * DM];
__device__ float  g_xc[BL * DM];
__device__ __half g_xch[BL * DM];
__device__ float  g_projp[KSPLIT * BL * NPROJ];  // split-K partials
__device__ float  g_proj[BL * NPROJ];
__device__ __half g_projh[BL * NPROJ];
__device__ float  g_delta[BL * DM];
__device__ __half g_yh[BL * DM];
__device__ __half g_Wth_inres[2 * DM * DIN];
__device__ __half g_Wth_out[DIN * DM];
__device__ __half g_Wth_cat[NPROJ * DM];
__device__ __half g_Wth_dtw[DM * DR];

// ---------------- helpers ----------------
__device__ __forceinline__ void mma_f16(float* c, const uint32_t* a, const uint32_t* b) {
    asm volatile(
        "mma.sync.aligned.m16n8k16.row.col.f32.f16.f16.f32 "
        "{%0,%1,%2,%3}, {%4,%5,%6,%7}, {%8,%9}, {%0,%1,%2,%3};"
        : "+f"(c[0]), "+f"(c[1]), "+f"(c[2]), "+f"(c[3])
        : "r"(a[0]), "r"(a[1]), "r"(a[2]), "r"(a[3]), "r"(b[0]), "r"(b[1]));
}
__device__ __forceinline__ void ldmx4(uint32_t* r, uint32_t addr) {
    asm volatile("ldmatrix.sync.aligned.m8n8.x4.shared.b16 {%0,%1,%2,%3}, [%4];"
        : "=r"(r[0]), "=r"(r[1]), "=r"(r[2]), "=r"(r[3]) : "r"(addr));
}
__device__ __forceinline__ void cpa16(uint32_t dst, const void* src) {
    asm volatile("cp.async.cg.shared.global [%0], [%1], 16;" :: "r"(dst), "l"(src));
}
__device__ __forceinline__ void cpa16z(uint32_t dst, const void* src, int srcbytes) {
    asm volatile("cp.async.cg.shared.global [%0], [%1], 16, %2;"
                 :: "r"(dst), "l"(src), "r"(srcbytes));
}
__device__ __forceinline__ void cpa_commit() { asm volatile("cp.async.commit_group;"); }
__device__ __forceinline__ void cpa_wait1()  { asm volatile("cp.async.wait_group 1;" ::: "memory"); }
__device__ __forceinline__ void cpa_wait0()  { asm volatile("cp.async.wait_group 0;" ::: "memory"); }

// ============ fp16 mma GEMM: 128x128 CTA tile, BK=32, 3-stage cp.async, ldmatrix ========
// C(M x N) = A(M x K) @ Bt(N x K)^T.  Split-K via gridDim.z: z-slice kz handles
// K/kdiv contraction cols, output goes to C + kz*pstride.
// EPI: 0=none, 2=softplus(+bias), 4=dual: col<DM -> C, col>=DM -> C2 with silu
template<int EPI>
__global__ void __launch_bounds__(256, 2) gemm_h(
    const __half* __restrict__ A, int lda,
    const __half* __restrict__ Bt,
    float* __restrict__ C, float* __restrict__ C2, int ldc,
    const float* __restrict__ bias, int N, int K,
    int kdiv, size_t pstride)
{
    constexpr int ABUF = 128 * 64;
    constexpr int BBUF = 128 * 64;
    extern __shared__ char sh[];
    const uint32_t sA = (uint32_t)__cvta_generic_to_shared(sh);
    const uint32_t sB = sA + 3 * ABUF;

    const int tid  = threadIdx.x;
    const int wid  = tid >> 5, lane = tid & 31;
    const int gid  = lane >> 2, tig = lane & 3;
    const int bm   = blockIdx.y * 128, bn = blockIdx.x * 128;
    const int wm   = (wid >> 2) * 64;
    const int wn   = (wid & 3) * 32;

    const int Keff = K / kdiv;
    const int koff = blockIdx.z * Keff;
    float* Cout = C + (size_t)blockIdx.z * pstride;

    float acc[4][4][4] = {};

    const int lrow = tid >> 1;
    const int lq   = (tid & 1) * 2;
    const int swr  = (lrow & 7) >> 1;
    const uint32_t dA0 = sA + (uint32_t)(lrow * 64 + (((lq    ) ^ swr) << 4));
    const uint32_t dA1 = sA + (uint32_t)(lrow * 64 + (((lq + 1) ^ swr) << 4));
    const __half* Ag = A + (size_t)(bm + lrow) * lda + koff + lq * 8;

    const int brow = bn + lrow;
    const __half* Bg = Bt + (size_t)brow * K + koff + lq * 8;
    const uint32_t dB0 = sB + (uint32_t)(lrow * 64 + (((lq    ) ^ swr) << 4));
    const uint32_t dB1 = sB + (uint32_t)(lrow * 64 + (((lq + 1) ^ swr) << 4));
    const int bbytes = (brow < N) ? 16 : 0;

    const int NC = Keff >> 5;

    auto issue = [&](int c) {
        const int buf = c % 3;
        const int ko  = c * 32;
        cpa16(dA0 + buf * ABUF, Ag + ko);
        cpa16(dA1 + buf * ABUF, Ag + ko + 8);
        cpa16z(dB0 + buf * BBUF, Bg + ko,     bbytes);
        cpa16z(dB1 + buf * BBUF, Bg + ko + 8, bbytes);
        cpa_commit();
    };

    const int swl = (lane & 7) >> 1;
    const uint32_t aLm = sA + (uint32_t)((wm + (lane & 15)) * 64);
    const int aQ = lane >> 4;
    const uint32_t bLm = sB + (uint32_t)((wn + (lane & 7) + ((lane >> 4) & 1) * 8) * 64);
    const int bQ = (lane >> 3) & 1;

    issue(0);
    issue(1);

    for (int c = 0; c < NC; ++c) {
        cpa_wait1();
        __syncthreads();
        if (c + 2 < NC) issue(c + 2);

        const int buf = c % 3;
        const uint32_t Ab = aLm + buf * ABUF;
        const uint32_t Bb = bLm + buf * BBUF;
        #pragma unroll
        for (int ks = 0; ks < 2; ++ks) {
            uint32_t af[4][4], bf[4][2];
            const uint32_t qa = (uint32_t)(((aQ + 2 * ks) ^ swl) << 4);
            const uint32_t qb = (uint32_t)(((bQ + 2 * ks) ^ swl) << 4);
            #pragma unroll
            for (int i = 0; i < 4; ++i)
                ldmx4(af[i], Ab + i * 1024 + qa);
            #pragma unroll
            for (int jj = 0; jj < 2; ++jj)
                ldmx4(&bf[2 * jj][0], Bb + jj * 1024 + qb);
            #pragma unroll
            for (int i = 0; i < 4; ++i)
                #pragma unroll
                for (int j = 0; j < 4; ++j)
                    mma_f16(acc[i][j], af[i], bf[j]);
        }
    }

    __syncthreads();

    #pragma unroll
    for (int i = 0; i < 4; ++i) {
        const int r0 = bm + wm + i * 16 + gid;
        #pragma unroll
        for (int j = 0; j < 4; ++j) {
            const int col = bn + wn + j * 8 + tig * 2;
            if (col >= N) continue;
            float v[4];
            #pragma unroll
            for (int q = 0; q < 4; ++q) v[q] = acc[i][j][q];
            if (EPI == 2) {
                const float bb0 = bias[col], bb1 = bias[col + 1];
                v[0] += bb0; v[1] += bb1; v[2] += bb0; v[3] += bb1;
                #pragma unroll
                for (int q = 0; q < 4; ++q)
                    v[q] = (v[q] > 20.0f) ? v[q] : log1pf(__expf(v[q]));
                *(float2*)(Cout + (size_t)r0 * ldc + col)       = make_float2(v[0], v[1]);
                *(float2*)(Cout + (size_t)(r0 + 8) * ldc + col) = make_float2(v[2], v[3]);
            } else if (EPI == 4) {
                if (col < DM) {
                    *(float2*)(Cout + (size_t)r0 * ldc + col)       = make_float2(v[0], v[1]);
                    *(float2*)(Cout + (size_t)(r0 + 8) * ldc + col) = make_float2(v[2], v[3]);
                } else {
                    #pragma unroll
                    for (int q = 0; q < 4; ++q) v[q] = v[q] / (1.0f + __expf(-v[q]));
                    const int cc = col - DM;
                    *(float2*)(C2 + (size_t)r0 * ldc + cc)       = make_float2(v[0], v[1]);
                    *(float2*)(C2 + (size_t)(r0 + 8) * ldc + cc) = make_float2(v[2], v[3]);
                }
            } else {
                *(float2*)(Cout + (size_t)r0 * ldc + col)       = make_float2(v[0], v[1]);
                *(float2*)(Cout + (size_t)(r0 + 8) * ldc + col) = make_float2(v[2], v[3]);
            }
        }
    }
}

// ---------------- split-K reduce: g_projp[4] -> g_proj (fp32) + g_projh (fp16) ----------
__global__ void proj_reduce()
{
    const int i = blockIdx.x * blockDim.x + threadIdx.x;
    if (i >= BL * NPROJ) return;
    float s = g_projp[i] + g_projp[BL * NPROJ + i]
            + g_projp[2 * BL * NPROJ + i] + g_projp[3 * BL * NPROJ + i];
    g_proj[i]  = s;
    g_projh[i] = __float2half(s);
}

// ---------------- transpose fp32 -> fp16 ----------------
__global__ void transpose_h(const float* __restrict__ in, __half* __restrict__ out,
                            int R, int Ccols)
{
    __shared__ float t[32][33];
    const int r0 = blockIdx.y * 32, c0 = blockIdx.x * 32;
    #pragma unroll
    for (int dy = 0; dy < 32; dy += 8) {
        const int r = r0 + threadIdx.y + dy, c = c0 + threadIdx.x;
        if (r < R && c < Ccols) t[threadIdx.y + dy][threadIdx.x] = in[(size_t)r * Ccols + c];
    }
    __syncthreads();
    #pragma unroll
    for (int dy = 0; dy < 32; dy += 8) {
        const int rr = c0 + threadIdx.y + dy, cc = r0 + threadIdx.x;
        if (rr < Ccols && cc < R)
            out[(size_t)rr * R + cc] = __float2half(t[threadIdx.x][threadIdx.y + dy]);
    }
}

// ---------------- combined small transposes ----------------
__global__ void transpose_small(const float* __restrict__ WB, const float* __restrict__ WC,
                                const float* __restrict__ Wdt, const float* __restrict__ dtw,
                                __half* __restrict__ cat, __half* __restrict__ dtwT)
{
    __shared__ float t[32][33];
    const float* in; __half* out; int R, Ccols, rb, cb;
    switch (blockIdx.z) {
        case 0: if (blockIdx.x) return;
                in = WB;  out = cat;               R = DM; Ccols = DS; rb = blockIdx.y; cb = 0; break;
        case 1: if (blockIdx.x) return;
                in = WC;  out = cat + DS * DM;     R = DM; Ccols = DS; rb = blockIdx.y; cb = 0; break;
        case 2: in = Wdt; out = cat + 2 * DS * DM; R = DM; Ccols = DR; rb = blockIdx.y; cb = blockIdx.x; break;
        default:in = dtw; out = dtwT;              R = DR; Ccols = DM; rb = blockIdx.x; cb = blockIdx.y; break;
    }
    const int r0 = rb * 32, c0 = cb * 32;
    #pragma unroll
    for (int dy = 0; dy < 32; dy += 8) {
        const int r = r0 + threadIdx.y + dy, c = c0 + threadIdx.x;
        if (r < R && c < Ccols) t[threadIdx.y + dy][threadIdx.x] = in[(size_t)r * Ccols + c];
    }
    __syncthreads();
    #pragma unroll
    for (int dy = 0; dy < 32; dy += 8) {
        const int rr = c0 + threadIdx.y + dy, cc = r0 + threadIdx.x;
        if (rr < Ccols && cc < R)
            out[(size_t)rr * R + cc] = __float2half(t[threadIdx.x][threadIdx.y + dy]);
    }
}

__global__ void cvt_x(const float* __restrict__ in, int n)
{
    const int i = blockIdx.x * blockDim.x + threadIdx.x;
    if (i < n) g_xh[i] = __float2half(in[i]);
}

// ---------------- causal depthwise conv + SiLU ----------------
__global__ void conv_silu_kernel(const float* __restrict__ cw, const float* __restrict__ cb)
{
    const int idx = blockIdx.x * blockDim.x + threadIdx.x;
    if (idx >= BL * DM) return;
    const int d  = idx % DM;
    const int bl = idx / DM;
    const int l  = bl % L_;

    float v = cb[d];
    #pragma unroll
    for (int i = 0; i < KCONV; i++) {
        const int li = l - (KCONV - 1) + i;
        if (li >= 0)
            v = fmaf(g_x[idx + (li - l) * DM], cw[d * KCONV + i], v);
    }
    v = v / (1.0f + __expf(-v));
    g_xc[idx]  = v;
    g_xch[idx] = __float2half(v);
}

// ---------------- selective scan: smem-tiled, cp.async double-buffered ----------------
#define ST 64
__global__ __launch_bounds__(256) void scan_kernel(
    const float* __restrict__ A_log, const float* __restrict__ Dp)
{
    __shared__ float  sd[2][ST][16];
    __shared__ float  sx[2][ST][16];
    __shared__ float  sr[2][ST][16];
    __shared__ float  sp[2][ST][32];
    __shared__ __half sy[ST][16];

    const int tid = threadIdx.x;
    const int g = tid >> 4, n = tid & 15;
    const int b  = blockIdx.x / (DM / 16);
    const int d0 = (blockIdx.x % (DM / 16)) * 16;
    const int d  = d0 + g;

    const float a  = -__expf(A_log[d * DS + n]);
    const float Dd = Dp[d];

    const float* baseD = g_delta + (size_t)b * L_ * DM + d0;
    const float* baseX = g_xc    + (size_t)b * L_ * DM + d0;
    const float* baseR = g_res   + (size_t)b * L_ * DM + d0;
    const float* baseP = g_proj  + (size_t)b * L_ * NPROJ;
    __half*      baseY = g_yh    + (size_t)b * L_ * DM + d0;

    const int t4 = tid >> 2, q4 = tid & 3;
    const int t8 = tid >> 3, q8 = tid & 7;

    uint32_t aD = (uint32_t)__cvta_generic_to_shared(&sd[0][t4][q4 * 4]);
    uint32_t aX = (uint32_t)__cvta_generic_to_shared(&sx[0][t4][q4 * 4]);
    uint32_t aR = (uint32_t)__cvta_generic_to_shared(&sr[0][t4][q4 * 4]);
    uint32_t aP0 = (uint32_t)__cvta_generic_to_shared(&sp[0][t8][q8 * 4]);
    uint32_t aP1 = (uint32_t)__cvta_generic_to_shared(&sp[0][t8 + 32][q8 * 4]);
    const uint32_t bD = sizeof(float) * ST * 16;
    const uint32_t bP = sizeof(float) * ST * 32;

    auto stage = [&](int l0, int buf) {
        cpa16(aD + buf * bD, baseD + (size_t)(l0 + t4) * DM + q4 * 4);
        cpa16(aX + buf * bD, baseX + (size_t)(l0 + t4) * DM + q4 * 4);
        cpa16(aR + buf * bD, baseR + (size_t)(l0 + t4) * DM + q4 * 4);
        cpa16(aP0 + buf * bP, baseP + (size_t)(l0 + t8) * NPROJ + q8 * 4);
        cpa16(aP1 + buf * bP, baseP + (size_t)(l0 + t8 + 32) * NPROJ + q8 * 4);
        cpa_commit();
    };

    stage(0, 0);
    cpa_wait0();
    __syncthreads();

    float h = 0.0f;
    const int NT = L_ / ST;
    for (int tt = 0; tt < NT; ++tt) {
        const int buf = tt & 1;
        if (tt + 1 < NT) stage((tt + 1) * ST, buf ^ 1);

        #pragma unroll 4
        for (int t = 0; t < ST; ++t) {
            const float dlt = sd[buf][t][g];
            const float xv  = sx[buf][t][g];
            const float bv  = sp[buf][t][n];
            const float cv  = sp[buf][t][16 + n];

            const float dA = __expf(dlt * a);
            h = fmaf(dA, h, dlt * bv * xv);

            float py = h * cv;
            py += __shfl_xor_sync(0xffffffffu, py, 8);
            py += __shfl_xor_sync(0xffffffffu, py, 4);
            py += __shfl_xor_sync(0xffffffffu, py, 2);
            py += __shfl_xor_sync(0xffffffffu, py, 1);

            if (n == 0) {
                const float sil = sr[buf][t][g];
                sy[t][g] = __float2half((py + Dd * xv) * sil);
            }
        }
        cpa_wait0();
        __syncthreads();
        if (tid < 128) {
            const int row = tid >> 1, q = tid & 1;
            float4 v = *(float4*)(&sy[row][q * 8]);
            *(float4*)(baseY + (size_t)(tt * ST + row) * DM + q * 8) = v;
        }
        __syncthreads();
    }
}

// ---------------- launch ----------------
extern "C" void kernel_launch(void* const* d_in, const int* in_sizes, int n_in,
                              void* d_out, int out_size)
{
    const float* x_in   = (const float*)d_in[0];
    const float* W_in   = (const float*)d_in[1];
    const float* W_res  = (const float*)d_in[2];
    const float* W_out  = (const float*)d_in[3];
    const float* conv_w = (const float*)d_in[4];
    const float* conv_b = (const float*)d_in[5];
    const float* A_log  = (const float*)d_in[6];
    const float* Dvec   = (const float*)d_in[7];
    const float* W_B    = (const float*)d_in[8];
    const float* W_C    = (const float*)d_in[9];
    const float* W_dt   = (const float*)d_in[10];
    const float* dt_w   = (const float*)d_in[11];
    const float* dt_b   = (const float*)d_in[12];
    float* out = (float*)d_out;

    float  *px, *pres, *pxc, *pprojp, *pdelta;
    __half *pxh, *pxch, *pprojh, *pyh, *pWir, *pWto, *pWtc, *pWtd;
    cudaGetSymbolAddress((void**)&px,     g_x);
    cudaGetSymbolAddress((void**)&pres,   g_res);
    cudaGetSymbolAddress((void**)&pxc,    g_xc);
    cudaGetSymbolAddress((void**)&pprojp, g_projp);
    cudaGetSymbolAddress((void**)&pdelta, g_delta);
    cudaGetSymbolAddress((void**)&pxh,    g_xh);
    cudaGetSymbolAddress((void**)&pxch,   g_xch);
    cudaGetSymbolAddress((void**)&pprojh, g_projh);
    cudaGetSymbolAddress((void**)&pyh,    g_yh);
    cudaGetSymbolAddress((void**)&pWir,   g_Wth_inres);
    cudaGetSymbolAddress((void**)&pWto,   g_Wth_out);
    cudaGetSymbolAddress((void**)&pWtc,   g_Wth_cat);
    cudaGetSymbolAddress((void**)&pWtd,   g_Wth_dtw);

    const int smem = 3 * (128 * 64 + 128 * 64);   // 49152
    cudaFuncSetAttribute(gemm_h<4>, cudaFuncAttributeMaxDynamicSharedMemorySize, smem);
    cudaFuncSetAttribute(gemm_h<2>, cudaFuncAttributeMaxDynamicSharedMemorySize, smem);
    cudaFuncSetAttribute(gemm_h<0>, cudaFuncAttributeMaxDynamicSharedMemorySize, smem);

    dim3 tb(32, 8);
    transpose_h<<<dim3(DM / 32, DIN / 32), tb>>>(W_in,  pWir,            DIN, DM);
    transpose_h<<<dim3(DM / 32, DIN / 32), tb>>>(W_res, pWir + DM * DIN, DIN, DM);
    transpose_h<<<dim3(DIN / 32, DM / 32), tb>>>(W_out, pWto, DM, DIN);
    transpose_small<<<dim3(4, 64, 4), tb>>>(W_B, W_C, W_dt, dt_w, pWtc, pWtd);
    cvt_x<<<(BL * DIN + 255) / 256, 256>>>(x_in, BL * DIN);

    // fused in+res projection (N=4096), 128x128 tiles -> 512 CTAs
    gemm_h<4><<<dim3(32, 16), 256, smem>>>(
        pxh, DIN, pWir, px, pres, DM, nullptr, 2 * DM, DIN, 1, 0);

    // conv + silu
    conv_silu_kernel<<<(BL * DM + 255) / 256, 256>>>(conv_w, conv_b);

    // fused skinny projections (N=160), split-K x4 -> partials
    gemm_h<0><<<dim3(2, 16, KSPLIT), 256, smem>>>(
        pxch, DM, pWtc, pprojp, nullptr, NPROJ, nullptr, NPROJ, DM,
        KSPLIT, (size_t)BL * NPROJ);
    proj_reduce<<<(BL * NPROJ + 255) / 256, 256>>>();

    // delta = softplus(dtr @ dt_w + dt_b) -> 256 CTAs
    gemm_h<2><<<dim3(16, 16), 256, smem>>>(
        pprojh + 2 * DS, NPROJ, pWtd, pdelta, nullptr, DM, dt_b, DM, DR, 1, 0);

    // selective scan
    scan_kernel<<<B_ * DM / 16, 256>>>(A_log, Dvec);

    // output projection (N=1024) -> 128 CTAs
    gemm_h<0><<<dim3(8, 16), 256, smem>>>(
        pyh, DM, pWto, out, nullptr, DIN, nullptr, DIN, DM, 1, 0);
}

// round 8
// speedup vs baseline: 6.2287x; 1.0999x over previous
#include <cuda_runtime.h>
#include <cuda_fp16.h>
#include <math.h>
#include <stdint.h>

#define B_    2
#define L_    1024
#define DIN   1024
#define DM    2048
#define DS    16
#define DR    128
#define KCONV 4
#define BL    (B_ * L_)
#define NPROJ 160
#define KSPLIT 4

// ---------------- scratch ----------------
__device__ __half g_xh[BL * DIN];            // fp16 x_in
__device__ __half g_xm_h[BL * DM];           // fp16 x = x_in @ W_in (conv input)
__device__ float  g_res[BL * DM];            // silu(x_in @ W_res)
__device__ float  g_xc[BL * DM];             // silu(conv(x)) fp32 (scan)
__device__ __half g_xch[BL * DM];            // fp16 copy (GEMM A)
__device__ float  g_projp[KSPLIT * BL * NPROJ];
__device__ float  g_proj[BL * NPROJ];
__device__ __half g_projh[BL * NPROJ];
__device__ float  g_delta[BL * DM];
__device__ __half g_yh[BL * DM];
__device__ __half g_Wth_inres[2 * DM * DIN];
__device__ __half g_Wth_out[DIN * DM];
__device__ __half g_Wth_cat[NPROJ * DM];
__device__ __half g_Wth_dtw[DM * DR];

// ---------------- helpers ----------------
__device__ __forceinline__ void mma_f16(float* c, const uint32_t* a, const uint32_t* b) {
    asm volatile(
        "mma.sync.aligned.m16n8k16.row.col.f32.f16.f16.f32 "
        "{%0,%1,%2,%3}, {%4,%5,%6,%7}, {%8,%9}, {%0,%1,%2,%3};"
        : "+f"(c[0]), "+f"(c[1]), "+f"(c[2]), "+f"(c[3])
        : "r"(a[0]), "r"(a[1]), "r"(a[2]), "r"(a[3]), "r"(b[0]), "r"(b[1]));
}
__device__ __forceinline__ void ldmx4(uint32_t* r, uint32_t addr) {
    asm volatile("ldmatrix.sync.aligned.m8n8.x4.shared.b16 {%0,%1,%2,%3}, [%4];"
        : "=r"(r[0]), "=r"(r[1]), "=r"(r[2]), "=r"(r[3]) : "r"(addr));
}
__device__ __forceinline__ void cpa16(uint32_t dst, const void* src) {
    asm volatile("cp.async.cg.shared.global [%0], [%1], 16;" :: "r"(dst), "l"(src));
}
__device__ __forceinline__ void cpa16z(uint32_t dst, const void* src, int srcbytes) {
    asm volatile("cp.async.cg.shared.global [%0], [%1], 16, %2;"
                 :: "r"(dst), "l"(src), "r"(srcbytes));
}
__device__ __forceinline__ void cpa_commit() { asm volatile("cp.async.commit_group;"); }
__device__ __forceinline__ void cpa_wait1()  { asm volatile("cp.async.wait_group 1;" ::: "memory"); }
__device__ __forceinline__ void cpa_wait0()  { asm volatile("cp.async.wait_group 0;" ::: "memory"); }

// ============ fp16 mma GEMM: MTx128 CTA tile, BK=32, 3-stage cp.async, ldmatrix ========
// C(M x N) = A(M x K) @ Bt(N x K)^T. Split-K via gridDim.z (kdiv slices, partials at
// C + z*pstride). MT in {64,128}.
// EPI: 0=plain fp32, 2=softplus(+bias) fp32, 4=dual: col<DM -> fp16 Hx, col>=DM -> silu fp32 C2
template<int MT, int EPI>
__global__ void __launch_bounds__(256, 2) gemm_h(
    const __half* __restrict__ A, int lda,
    const __half* __restrict__ Bt,
    float* __restrict__ C, float* __restrict__ C2, __half* __restrict__ Hx, int ldc,
    const float* __restrict__ bias, int N, int K,
    int kdiv, size_t pstride)
{
    constexpr int ABUF = MT * 64;
    constexpr int BBUF = 128 * 64;
    constexpr int MI   = MT / 32;          // m-atoms per warp tile
    extern __shared__ char sh[];
    const uint32_t sA = (uint32_t)__cvta_generic_to_shared(sh);
    const uint32_t sB = sA + 3 * ABUF;

    const int tid  = threadIdx.x;
    const int wid  = tid >> 5, lane = tid & 31;
    const int gid  = lane >> 2, tig = lane & 3;
    const int bm   = blockIdx.y * MT, bn = blockIdx.x * 128;
    const int wm   = (wid >> 2) * (MT / 2);
    const int wn   = (wid & 3) * 32;

    const int Keff = K / kdiv;
    const int koff = blockIdx.z * Keff;
    float* Cout = C + (size_t)blockIdx.z * pstride;

    float acc[MI][4][4] = {};

    const int NC = Keff >> 5;

    auto issue = [&](int c) {
        const int buf = c % 3;
        const int ko  = koff + c * 32;
        #pragma unroll
        for (int it = 0; it < (MT * 4 + 255) / 256; ++it) {
            const int i = tid + it * 256;
            if (i < MT * 4) {
                const int row = i >> 2, q = i & 3;
                const int sw = q ^ ((row & 7) >> 1);
                cpa16(sA + buf * ABUF + (uint32_t)(row * 64 + sw * 16),
                      A + (size_t)(bm + row) * lda + ko + q * 8);
            }
        }
        #pragma unroll
        for (int it = 0; it < 2; ++it) {
            const int i = tid + it * 256;
            const int row = i >> 2, q = i & 3;
            const int sw = q ^ ((row & 7) >> 1);
            const int brow = bn + row;
            cpa16z(sB + buf * BBUF + (uint32_t)(row * 64 + sw * 16),
                   Bt + (size_t)brow * K + ko + q * 8,
                   (brow < N) ? 16 : 0);
        }
        cpa_commit();
    };

    const int swl = (lane & 7) >> 1;
    const uint32_t aLm = sA + (uint32_t)((wm + (lane & 15)) * 64);
    const int aQ = lane >> 4;
    const uint32_t bLm = sB + (uint32_t)((wn + (lane & 7) + ((lane >> 4) & 1) * 8) * 64);
    const int bQ = (lane >> 3) & 1;

    issue(0);
    issue(1);

    for (int c = 0; c < NC; ++c) {
        cpa_wait1();
        __syncthreads();
        if (c + 2 < NC) issue(c + 2);

        const int buf = c % 3;
        const uint32_t Ab = aLm + buf * ABUF;
        const uint32_t Bb = bLm + buf * BBUF;
        #pragma unroll
        for (int ks = 0; ks < 2; ++ks) {
            uint32_t af[MI][4], bf[4][2];
            const uint32_t qa = (uint32_t)(((aQ + 2 * ks) ^ swl) << 4);
            const uint32_t qb = (uint32_t)(((bQ + 2 * ks) ^ swl) << 4);
            #pragma unroll
            for (int i = 0; i < MI; ++i)
                ldmx4(af[i], Ab + i * 1024 + qa);
            #pragma unroll
            for (int jj = 0; jj < 2; ++jj)
                ldmx4(&bf[2 * jj][0], Bb + jj * 1024 + qb);
            #pragma unroll
            for (int i = 0; i < MI; ++i)
                #pragma unroll
                for (int j = 0; j < 4; ++j)
                    mma_f16(acc[i][j], af[i], bf[j]);
        }
    }

    __syncthreads();

    #pragma unroll
    for (int i = 0; i < MI; ++i) {
        const int r0 = bm + wm + i * 16 + gid;
        #pragma unroll
        for (int j = 0; j < 4; ++j) {
            const int col = bn + wn + j * 8 + tig * 2;
            if (col >= N) continue;
            float v[4];
            #pragma unroll
            for (int q = 0; q < 4; ++q) v[q] = acc[i][j][q];
            if (EPI == 2) {
                const float bb0 = bias[col], bb1 = bias[col + 1];
                v[0] += bb0; v[1] += bb1; v[2] += bb0; v[3] += bb1;
                #pragma unroll
                for (int q = 0; q < 4; ++q)
                    v[q] = (v[q] > 20.0f) ? v[q] : log1pf(__expf(v[q]));
                *(float2*)(Cout + (size_t)r0 * ldc + col)       = make_float2(v[0], v[1]);
                *(float2*)(Cout + (size_t)(r0 + 8) * ldc + col) = make_float2(v[2], v[3]);
            } else if (EPI == 4) {
                if (col < DM) {
                    *(__half2*)(Hx + (size_t)r0 * ldc + col)       = __floats2half2_rn(v[0], v[1]);
                    *(__half2*)(Hx + (size_t)(r0 + 8) * ldc + col) = __floats2half2_rn(v[2], v[3]);
                } else {
                    #pragma unroll
                    for (int q = 0; q < 4; ++q) v[q] = v[q] / (1.0f + __expf(-v[q]));
                    const int cc = col - DM;
                    *(float2*)(C2 + (size_t)r0 * ldc + cc)       = make_float2(v[0], v[1]);
                    *(float2*)(C2 + (size_t)(r0 + 8) * ldc + cc) = make_float2(v[2], v[3]);
                }
            } else {
                *(float2*)(Cout + (size_t)r0 * ldc + col)       = make_float2(v[0], v[1]);
                *(float2*)(Cout + (size_t)(r0 + 8) * ldc + col) = make_float2(v[2], v[3]);
            }
        }
    }
}

// ---------------- split-K reduce: g_projp[4] -> g_proj (fp32) + g_projh (fp16) ----------
__global__ void proj_reduce()
{
    const int i = blockIdx.x * blockDim.x + threadIdx.x;
    if (i >= BL * NPROJ) return;
    float s = g_projp[i] + g_projp[BL * NPROJ + i]
            + g_projp[2 * BL * NPROJ + i] + g_projp[3 * BL * NPROJ + i];
    g_proj[i]  = s;
    g_projh[i] = __float2half(s);
}

// ---------------- one-shot prep: all weight transposes + x conversion ----------------
__device__ __forceinline__ void tr_body(const float* in, __half* out, int R, int Ccols,
                                        int rb, int cb, int tx, int ty)
{
    __shared__ float t[32][33];
    const int r0 = rb * 32, c0 = cb * 32;
    #pragma unroll
    for (int dy = 0; dy < 32; dy += 8) {
        const int r = r0 + ty + dy, c = c0 + tx;
        if (r < R && c < Ccols) t[ty + dy][tx] = in[(size_t)r * Ccols + c];
    }
    __syncthreads();
    #pragma unroll
    for (int dy = 0; dy < 32; dy += 8) {
        const int rr = c0 + ty + dy, cc = r0 + tx;
        if (rr < Ccols && cc < R)
            out[(size_t)rr * R + cc] = __float2half(t[tx][ty + dy]);
    }
}

__global__ void prep(const float* __restrict__ W_in, const float* __restrict__ W_res,
                     const float* __restrict__ W_out, const float* __restrict__ WB,
                     const float* __restrict__ WC, const float* __restrict__ Wdt,
                     const float* __restrict__ dtw, const float* __restrict__ x_in)
{
    const int tx = threadIdx.x, ty = threadIdx.y;
    const int bx = blockIdx.x, by = blockIdx.y;
    switch (blockIdx.z) {
        case 0:  // W_in: (DIN x DM) -> Wth_inres[0]
            if (by < DIN / 32) tr_body(W_in, g_Wth_inres, DIN, DM, by, bx, tx, ty);
            return;
        case 1:  // W_res
            if (by < DIN / 32) tr_body(W_res, g_Wth_inres + DM * DIN, DIN, DM, by, bx, tx, ty);
            return;
        case 2:  // W_out: (DM x DIN) -> Wth_out
            if (bx < DIN / 32) tr_body(W_out, g_Wth_out, DM, DIN, by, bx, tx, ty);
            return;
        case 3:  // small weights
            if (bx == 0)            tr_body(WB,  g_Wth_cat,               DM, DS, by, 0, tx, ty);
            else if (bx == 1)       tr_body(WC,  g_Wth_cat + DS * DM,     DM, DS, by, 0, tx, ty);
            else if (bx < 6)        tr_body(Wdt, g_Wth_cat + 2 * DS * DM, DM, DR, by, bx - 2, tx, ty);
            else if (bx < 10 && bx - 6 < DR / 32)
                                    tr_body(dtw, g_Wth_dtw,               DR, DM, bx - 6, by, tx, ty);
            return;
        default: {  // x_in -> fp16
            const int tid = ty * 32 + tx;
            const int bid = by * gridDim.x + bx;
            const int i = bid * 256 + tid;
            if (i < BL * DIN / 4) {
                float4 v = *(const float4*)(x_in + (size_t)i * 4);
                __half2 h0 = __floats2half2_rn(v.x, v.y);
                __half2 h1 = __floats2half2_rn(v.z, v.w);
                *(__half2*)(g_xh + (size_t)i * 4)     = h0;
                *(__half2*)(g_xh + (size_t)i * 4 + 2) = h1;
            }
            return;
        }
    }
}

// ---------------- causal depthwise conv + SiLU (fp16 input) ----------------
__global__ void conv_silu_kernel(const float* __restrict__ cw, const float* __restrict__ cb)
{
    const int idx = blockIdx.x * blockDim.x + threadIdx.x;
    if (idx >= BL * DM) return;
    const int d  = idx % DM;
    const int bl = idx / DM;
    const int l  = bl % L_;

    float v = cb[d];
    #pragma unroll
    for (int i = 0; i < KCONV; i++) {
        const int li = l - (KCONV - 1) + i;
        if (li >= 0)
            v = fmaf(__half2float(g_xm_h[idx + (li - l) * DM]), cw[d * KCONV + i], v);
    }
    v = v / (1.0f + __expf(-v));
    g_xc[idx]  = v;
    g_xch[idx] = __float2half(v);
}

// ---------------- selective scan: smem-tiled, cp.async double-buffered ----------------
#define ST 64
__global__ __launch_bounds__(256) void scan_kernel(
    const float* __restrict__ A_log, const float* __restrict__ Dp)
{
    __shared__ float  sd[2][ST][16];
    __shared__ float  sx[2][ST][16];
    __shared__ float  sr[2][ST][16];
    __shared__ float  sp[2][ST][32];
    __shared__ __half sy[ST][16];

    const int tid = threadIdx.x;
    const int g = tid >> 4, n = tid & 15;
    const int b  = blockIdx.x / (DM / 16);
    const int d0 = (blockIdx.x % (DM / 16)) * 16;
    const int d  = d0 + g;

    const float a  = -__expf(A_log[d * DS + n]);
    const float Dd = Dp[d];

    const float* baseD = g_delta + (size_t)b * L_ * DM + d0;
    const float* baseX = g_xc    + (size_t)b * L_ * DM + d0;
    const float* baseR = g_res   + (size_t)b * L_ * DM + d0;
    const float* baseP = g_proj  + (size_t)b * L_ * NPROJ;
    __half*      baseY = g_yh    + (size_t)b * L_ * DM + d0;

    const int t4 = tid >> 2, q4 = tid & 3;
    const int t8 = tid >> 3, q8 = tid & 7;

    uint32_t aD = (uint32_t)__cvta_generic_to_shared(&sd[0][t4][q4 * 4]);
    uint32_t aX = (uint32_t)__cvta_generic_to_shared(&sx[0][t4][q4 * 4]);
    uint32_t aR = (uint32_t)__cvta_generic_to_shared(&sr[0][t4][q4 * 4]);
    uint32_t aP0 = (uint32_t)__cvta_generic_to_shared(&sp[0][t8][q8 * 4]);
    uint32_t aP1 = (uint32_t)__cvta_generic_to_shared(&sp[0][t8 + 32][q8 * 4]);
    const uint32_t bD = sizeof(float) * ST * 16;
    const uint32_t bP = sizeof(float) * ST * 32;

    auto stage = [&](int l0, int buf) {
        cpa16(aD + buf * bD, baseD + (size_t)(l0 + t4) * DM + q4 * 4);
        cpa16(aX + buf * bD, baseX + (size_t)(l0 + t4) * DM + q4 * 4);
        cpa16(aR + buf * bD, baseR + (size_t)(l0 + t4) * DM + q4 * 4);
        cpa16(aP0 + buf * bP, baseP + (size_t)(l0 + t8) * NPROJ + q8 * 4);
        cpa16(aP1 + buf * bP, baseP + (size_t)(l0 + t8 + 32) * NPROJ + q8 * 4);
        cpa_commit();
    };

    stage(0, 0);
    cpa_wait0();
    __syncthreads();

    float h = 0.0f;
    const int NT = L_ / ST;
    for (int tt = 0; tt < NT; ++tt) {
        const int buf = tt & 1;
        if (tt + 1 < NT) stage((tt + 1) * ST, buf ^ 1);

        #pragma unroll 4
        for (int t = 0; t < ST; ++t) {
            const float dlt = sd[buf][t][g];
            const float xv  = sx[buf][t][g];
            const float bv  = sp[buf][t][n];
            const float cv  = sp[buf][t][16 + n];

            const float dA = __expf(dlt * a);
            h = fmaf(dA, h, dlt * bv * xv);

            float py = h * cv;
            py += __shfl_xor_sync(0xffffffffu, py, 8);
            py += __shfl_xor_sync(0xffffffffu, py, 4);
            py += __shfl_xor_sync(0xffffffffu, py, 2);
            py += __shfl_xor_sync(0xffffffffu, py, 1);

            if (n == 0) {
                const float sil = sr[buf][t][g];
                sy[t][g] = __float2half((py + Dd * xv) * sil);
            }
        }
        cpa_wait0();
        __syncthreads();
        if (tid < 128) {
            const int row = tid >> 1, q = tid & 1;
            float4 v = *(float4*)(&sy[row][q * 8]);
            *(float4*)(baseY + (size_t)(tt * ST + row) * DM + q * 8) = v;
        }
        __syncthreads();
    }
}

// ---------------- launch ----------------
extern "C" void kernel_launch(void* const* d_in, const int* in_sizes, int n_in,
                              void* d_out, int out_size)
{
    const float* x_in   = (const float*)d_in[0];
    const float* W_in   = (const float*)d_in[1];
    const float* W_res  = (const float*)d_in[2];
    const float* W_out  = (const float*)d_in[3];
    const float* conv_w = (const float*)d_in[4];
    const float* conv_b = (const float*)d_in[5];
    const float* A_log  = (const float*)d_in[6];
    const float* Dvec   = (const float*)d_in[7];
    const float* W_B    = (const float*)d_in[8];
    const float* W_C    = (const float*)d_in[9];
    const float* W_dt   = (const float*)d_in[10];
    const float* dt_w   = (const float*)d_in[11];
    const float* dt_b   = (const float*)d_in[12];
    float* out = (float*)d_out;

    float  *pres, *pprojp, *pdelta;
    __half *pxh, *pxmh, *pxch, *pprojh, *pyh, *pWir, *pWto, *pWtc, *pWtd;
    cudaGetSymbolAddress((void**)&pres,   g_res);
    cudaGetSymbolAddress((void**)&pprojp, g_projp);
    cudaGetSymbolAddress((void**)&pdelta, g_delta);
    cudaGetSymbolAddress((void**)&pxh,    g_xh);
    cudaGetSymbolAddress((void**)&pxmh,   g_xm_h);
    cudaGetSymbolAddress((void**)&pxch,   g_xch);
    cudaGetSymbolAddress((void**)&pprojh, g_projh);
    cudaGetSymbolAddress((void**)&pyh,    g_yh);
    cudaGetSymbolAddress((void**)&pWir,   g_Wth_inres);
    cudaGetSymbolAddress((void**)&pWto,   g_Wth_out);
    cudaGetSymbolAddress((void**)&pWtc,   g_Wth_cat);
    cudaGetSymbolAddress((void**)&pWtd,   g_Wth_dtw);

    const int smem128 = 3 * (128 * 64 + 128 * 64);   // 49152
    const int smem64  = 3 * (64 * 64 + 128 * 64);    // 36864
    cudaFuncSetAttribute(gemm_h<128, 4>, cudaFuncAttributeMaxDynamicSharedMemorySize, smem128);
    cudaFuncSetAttribute(gemm_h<128, 0>, cudaFuncAttributeMaxDynamicSharedMemorySize, smem128);
    cudaFuncSetAttribute(gemm_h<64, 2>,  cudaFuncAttributeMaxDynamicSharedMemorySize, smem64);
    cudaFuncSetAttribute(gemm_h<64, 0>,  cudaFuncAttributeMaxDynamicSharedMemorySize, smem64);

    // 0: all prep in one kernel
    prep<<<dim3(64, 64, 5), dim3(32, 8)>>>(W_in, W_res, W_out, W_B, W_C, W_dt, dt_w, x_in);

    // 1: fused in+res projection (N=4096): x -> fp16, res -> silu fp32
    gemm_h<128, 4><<<dim3(32, 16), 256, smem128>>>(
        pxh, DIN, pWir, nullptr, pres, pxmh, DM, nullptr, 2 * DM, DIN, 1, 0);

    // 2: conv + silu
    conv_silu_kernel<<<(BL * DM + 255) / 256, 256>>>(conv_w, conv_b);

    // 3: fused skinny projections (N=160), split-K x4
    gemm_h<128, 0><<<dim3(2, 16, KSPLIT), 256, smem128>>>(
        pxch, DM, pWtc, pprojp, nullptr, nullptr, NPROJ, nullptr, NPROJ, DM,
        KSPLIT, (size_t)BL * NPROJ);

    // 4: reduce partials
    proj_reduce<<<(BL * NPROJ + 255) / 256, 256>>>();

    // 5: delta = softplus(dtr @ dt_w + dt_b), 64-row tiles -> 512 CTAs
    gemm_h<64, 2><<<dim3(16, 32), 256, smem64>>>(
        pprojh + 2 * DS, NPROJ, pWtd, pdelta, nullptr, nullptr, DM, dt_b, DM, DR, 1, 0);

    // 6: selective scan
    scan_kernel<<<B_ * DM / 16, 256>>>(A_log, Dvec);

    // 7: output projection (N=1024), 64-row tiles -> 256 CTAs
    gemm_h<64, 0><<<dim3(8, 32), 256, smem64>>>(
        pyh, DM, pWto, out, nullptr, nullptr, DIN, nullptr, DIN, DM, 1, 0);
}

// round 9
// speedup vs baseline: 6.4624x; 1.0375x over previous
#include <cuda_runtime.h>
#include <cuda_fp16.h>
#include <math.h>
#include <stdint.h>

#define B_    2
#define L_    1024
#define DIN   1024
#define DM    2048
#define DS    16
#define DR    128
#define KCONV 4
#define BL    (B_ * L_)
#define NPROJ 160
#define KSPLIT 8

// ---------------- scratch ----------------
__device__ __half g_xh[BL * DIN];            // fp16 x_in
__device__ __half g_xm_h[BL * DM];           // fp16 x = x_in @ W_in (conv input)
__device__ float  g_res[BL * DM];            // silu(x_in @ W_res)
__device__ float  g_xc[BL * DM];             // silu(conv(x)) fp32 (scan)
__device__ __half g_xch[BL * DM];            // fp16 copy (GEMM A)
__device__ float  g_projp[KSPLIT * BL * NPROJ];
__device__ float  g_proj[BL * NPROJ];
__device__ __half g_projh[BL * NPROJ];
__device__ float  g_delta[BL * DM];
__device__ __half g_yh[BL * DM];
__device__ __half g_Wth_inres[2 * DM * DIN];
__device__ __half g_Wth_out[DIN * DM];
__device__ __half g_Wth_cat[NPROJ * DM];
__device__ __half g_Wth_dtw[DM * DR];

// ---------------- helpers ----------------
__device__ __forceinline__ void mma_f16(float* c, const uint32_t* a, const uint32_t* b) {
    asm volatile(
        "mma.sync.aligned.m16n8k16.row.col.f32.f16.f16.f32 "
        "{%0,%1,%2,%3}, {%4,%5,%6,%7}, {%8,%9}, {%0,%1,%2,%3};"
        : "+f"(c[0]), "+f"(c[1]), "+f"(c[2]), "+f"(c[3])
        : "r"(a[0]), "r"(a[1]), "r"(a[2]), "r"(a[3]), "r"(b[0]), "r"(b[1]));
}
__device__ __forceinline__ void ldmx4(uint32_t* r, uint32_t addr) {
    asm volatile("ldmatrix.sync.aligned.m8n8.x4.shared.b16 {%0,%1,%2,%3}, [%4];"
        : "=r"(r[0]), "=r"(r[1]), "=r"(r[2]), "=r"(r[3]) : "r"(addr));
}
__device__ __forceinline__ void cpa16(uint32_t dst, const void* src) {
    asm volatile("cp.async.cg.shared.global [%0], [%1], 16;" :: "r"(dst), "l"(src));
}
__device__ __forceinline__ void cpa16z(uint32_t dst, const void* src, int srcbytes) {
    asm volatile("cp.async.cg.shared.global [%0], [%1], 16, %2;"
                 :: "r"(dst), "l"(src), "r"(srcbytes));
}
__device__ __forceinline__ void cpa_commit() { asm volatile("cp.async.commit_group;"); }
__device__ __forceinline__ void cpa_wait1()  { asm volatile("cp.async.wait_group 1;" ::: "memory"); }
__device__ __forceinline__ void cpa_wait0()  { asm volatile("cp.async.wait_group 0;" ::: "memory"); }

// ============ fp16 mma GEMM: MTx128 CTA tile, BK=64, 3-stage cp.async, ldmatrix ========
// C(M x N) = A(M x K) @ Bt(N x K)^T. Split-K via gridDim.z (kdiv slices, partials at
// C + z*pstride). MT in {64,128}. SMEM rows: 128B, SW128 swizzle quad ^ (row&7).
// EPI: 0=plain fp32, 2=softplus(+bias) fp32, 4=dual: col<DM -> fp16 Hx, col>=DM -> silu fp32 C2
template<int MT, int EPI>
__global__ void __launch_bounds__(256, 2) gemm_h(
    const __half* __restrict__ A, int lda,
    const __half* __restrict__ Bt,
    float* __restrict__ C, float* __restrict__ C2, __half* __restrict__ Hx, int ldc,
    const float* __restrict__ bias, int N, int K,
    int kdiv, size_t pstride)
{
    constexpr int ABUF = MT * 128;        // bytes per A stage (128B rows)
    constexpr int BBUF = 128 * 128;       // bytes per B stage
    constexpr int MI   = MT / 32;         // m-atoms per warp tile
    extern __shared__ char sh[];
    const uint32_t sA = (uint32_t)__cvta_generic_to_shared(sh);
    const uint32_t sB = sA + 3 * ABUF;

    const int tid  = threadIdx.x;
    const int wid  = tid >> 5, lane = tid & 31;
    const int gid  = lane >> 2, tig = lane & 3;
    const int bm   = blockIdx.y * MT, bn = blockIdx.x * 128;
    const int wm   = (wid >> 2) * (MT / 2);
    const int wn   = (wid & 3) * 32;

    const int Keff = K / kdiv;
    const int koff = blockIdx.z * Keff;
    float* Cout = C + (size_t)blockIdx.z * pstride;

    float acc[MI][4][4] = {};

    const int NC = Keff >> 6;             // 64-wide K chunks

    auto issue = [&](int c) {
        const int buf = c % 3;
        const int ko  = koff + c * 64;
        // A: MT rows x 8 quads
        #pragma unroll
        for (int it = 0; it < MT * 8 / 256; ++it) {
            const int i = tid + it * 256;
            const int row = i >> 3, q = i & 7;
            const int sw = q ^ (row & 7);
            cpa16(sA + buf * ABUF + (uint32_t)(row * 128 + sw * 16),
                  A + (size_t)(bm + row) * lda + ko + q * 8);
        }
        // B: 128 rows x 8 quads
        #pragma unroll
        for (int it = 0; it < 4; ++it) {
            const int i = tid + it * 256;
            const int row = i >> 3, q = i & 7;
            const int sw = q ^ (row & 7);
            const int brow = bn + row;
            cpa16z(sB + buf * BBUF + (uint32_t)(row * 128 + sw * 16),
                   Bt + (size_t)brow * K + ko + q * 8,
                   (brow < N) ? 16 : 0);
        }
        cpa_commit();
    };

    const int swl = lane & 7;
    const uint32_t aLm = sA + (uint32_t)((wm + (lane & 15)) * 128);
    const int aQ = lane >> 4;
    const uint32_t bLm = sB + (uint32_t)((wn + (lane & 7) + ((lane >> 4) & 1) * 8) * 128);
    const int bQ = (lane >> 3) & 1;

    issue(0);
    issue(1);

    for (int c = 0; c < NC; ++c) {
        if (c + 1 < NC) cpa_wait1(); else cpa_wait0();
        __syncthreads();
        if (c + 2 < NC) issue(c + 2);

        const int buf = c % 3;
        const uint32_t Ab = aLm + buf * ABUF;
        const uint32_t Bb = bLm + buf * BBUF;
        #pragma unroll
        for (int ks = 0; ks < 4; ++ks) {
            uint32_t af[MI][4], bf[4][2];
            const uint32_t qa = (uint32_t)(((aQ + 2 * ks) ^ swl) << 4);
            const uint32_t qb = (uint32_t)(((bQ + 2 * ks) ^ swl) << 4);
            #pragma unroll
            for (int i = 0; i < MI; ++i)
                ldmx4(af[i], Ab + i * 2048 + qa);
            #pragma unroll
            for (int jj = 0; jj < 2; ++jj)
                ldmx4(&bf[2 * jj][0], Bb + jj * 2048 + qb);
            #pragma unroll
            for (int i = 0; i < MI; ++i)
                #pragma unroll
                for (int j = 0; j < 4; ++j)
                    mma_f16(acc[i][j], af[i], bf[j]);
        }
    }

    __syncthreads();

    #pragma unroll
    for (int i = 0; i < MI; ++i) {
        const int r0 = bm + wm + i * 16 + gid;
        #pragma unroll
        for (int j = 0; j < 4; ++j) {
            const int col = bn + wn + j * 8 + tig * 2;
            if (col >= N) continue;
            float v[4];
            #pragma unroll
            for (int q = 0; q < 4; ++q) v[q] = acc[i][j][q];
            if (EPI == 2) {
                const float bb0 = bias[col], bb1 = bias[col + 1];
                v[0] += bb0; v[1] += bb1; v[2] += bb0; v[3] += bb1;
                #pragma unroll
                for (int q = 0; q < 4; ++q)
                    v[q] = (v[q] > 20.0f) ? v[q] : log1pf(__expf(v[q]));
                *(float2*)(Cout + (size_t)r0 * ldc + col)       = make_float2(v[0], v[1]);
                *(float2*)(Cout + (size_t)(r0 + 8) * ldc + col) = make_float2(v[2], v[3]);
            } else if (EPI == 4) {
                if (col < DM) {
                    *(__half2*)(Hx + (size_t)r0 * ldc + col)       = __floats2half2_rn(v[0], v[1]);
                    *(__half2*)(Hx + (size_t)(r0 + 8) * ldc + col) = __floats2half2_rn(v[2], v[3]);
                } else {
                    #pragma unroll
                    for (int q = 0; q < 4; ++q) v[q] = v[q] / (1.0f + __expf(-v[q]));
                    const int cc = col - DM;
                    *(float2*)(C2 + (size_t)r0 * ldc + cc)       = make_float2(v[0], v[1]);
                    *(float2*)(C2 + (size_t)(r0 + 8) * ldc + cc) = make_float2(v[2], v[3]);
                }
            } else {
                *(float2*)(Cout + (size_t)r0 * ldc + col)       = make_float2(v[0], v[1]);
                *(float2*)(Cout + (size_t)(r0 + 8) * ldc + col) = make_float2(v[2], v[3]);
            }
        }
    }
}

// ---------------- split-K reduce: g_projp[8] -> g_proj (fp32) + g_projh (fp16) ----------
__global__ void proj_reduce()
{
    const int i = blockIdx.x * blockDim.x + threadIdx.x;
    if (i >= BL * NPROJ) return;
    float s = 0.0f;
    #pragma unroll
    for (int z = 0; z < KSPLIT; ++z) s += g_projp[(size_t)z * BL * NPROJ + i];
    g_proj[i]  = s;
    g_projh[i] = __float2half(s);
}

// ---------------- one-shot prep: all weight transposes + x conversion ----------------
__device__ __forceinline__ void tr_body(const float* in, __half* out, int R, int Ccols,
                                        int rb, int cb, int tx, int ty)
{
    __shared__ float t[32][33];
    const int r0 = rb * 32, c0 = cb * 32;
    #pragma unroll
    for (int dy = 0; dy < 32; dy += 8) {
        const int r = r0 + ty + dy, c = c0 + tx;
        if (r < R && c < Ccols) t[ty + dy][tx] = in[(size_t)r * Ccols + c];
    }
    __syncthreads();
    #pragma unroll
    for (int dy = 0; dy < 32; dy += 8) {
        const int rr = c0 + ty + dy, cc = r0 + tx;
        if (rr < Ccols && cc < R)
            out[(size_t)rr * R + cc] = __float2half(t[tx][ty + dy]);
    }
}

__global__ void prep(const float* __restrict__ W_in, const float* __restrict__ W_res,
                     const float* __restrict__ W_out, const float* __restrict__ WB,
                     const float* __restrict__ WC, const float* __restrict__ Wdt,
                     const float* __restrict__ dtw, const float* __restrict__ x_in)
{
    const int tx = threadIdx.x, ty = threadIdx.y;
    const int bx = blockIdx.x, by = blockIdx.y;
    switch (blockIdx.z) {
        case 0:
            if (by < DIN / 32) tr_body(W_in, g_Wth_inres, DIN, DM, by, bx, tx, ty);
            return;
        case 1:
            if (by < DIN / 32) tr_body(W_res, g_Wth_inres + DM * DIN, DIN, DM, by, bx, tx, ty);
            return;
        case 2:
            if (bx < DIN / 32) tr_body(W_out, g_Wth_out, DM, DIN, by, bx, tx, ty);
            return;
        case 3:
            if (bx == 0)            tr_body(WB,  g_Wth_cat,               DM, DS, by, 0, tx, ty);
            else if (bx == 1)       tr_body(WC,  g_Wth_cat + DS * DM,     DM, DS, by, 0, tx, ty);
            else if (bx < 6)        tr_body(Wdt, g_Wth_cat + 2 * DS * DM, DM, DR, by, bx - 2, tx, ty);
            else if (bx < 10 && bx - 6 < DR / 32)
                                    tr_body(dtw, g_Wth_dtw,               DR, DM, bx - 6, by, tx, ty);
            return;
        default: {
            const int tid = ty * 32 + tx;
            const int bid = by * gridDim.x + bx;
            const int i = bid * 256 + tid;
            if (i < BL * DIN / 4) {
                float4 v = *(const float4*)(x_in + (size_t)i * 4);
                *(__half2*)(g_xh + (size_t)i * 4)     = __floats2half2_rn(v.x, v.y);
                *(__half2*)(g_xh + (size_t)i * 4 + 2) = __floats2half2_rn(v.z, v.w);
            }
            return;
        }
    }
}

// ---------------- causal depthwise conv + SiLU (fp16 input) ----------------
__global__ void conv_silu_kernel(const float* __restrict__ cw, const float* __restrict__ cb)
{
    const int idx = blockIdx.x * blockDim.x + threadIdx.x;
    if (idx >= BL * DM) return;
    const int d  = idx % DM;
    const int bl = idx / DM;
    const int l  = bl % L_;

    float v = cb[d];
    #pragma unroll
    for (int i = 0; i < KCONV; i++) {
        const int li = l - (KCONV - 1) + i;
        if (li >= 0)
            v = fmaf(__half2float(g_xm_h[idx + (li - l) * DM]), cw[d * KCONV + i], v);
    }
    v = v / (1.0f + __expf(-v));
    g_xc[idx]  = v;
    g_xch[idx] = __float2half(v);
}

// ---------------- selective scan: smem-tiled, cp.async double-buffered ----------------
#define ST 64
__global__ __launch_bounds__(256) void scan_kernel(
    const float* __restrict__ A_log, const float* __restrict__ Dp)
{
    __shared__ float  sd[2][ST][16];
    __shared__ float  sx[2][ST][16];
    __shared__ float  sr[2][ST][16];
    __shared__ float  sp[2][ST][32];
    __shared__ __half sy[ST][16];

    const int tid = threadIdx.x;
    const int g = tid >> 4, n = tid & 15;
    const int b  = blockIdx.x / (DM / 16);
    const int d0 = (blockIdx.x % (DM / 16)) * 16;
    const int d  = d0 + g;

    const float a  = -__expf(A_log[d * DS + n]);
    const float Dd = Dp[d];

    const float* baseD = g_delta + (size_t)b * L_ * DM + d0;
    const float* baseX = g_xc    + (size_t)b * L_ * DM + d0;
    const float* baseR = g_res   + (size_t)b * L_ * DM + d0;
    const float* baseP = g_proj  + (size_t)b * L_ * NPROJ;
    __half*      baseY = g_yh    + (size_t)b * L_ * DM + d0;

    const int t4 = tid >> 2, q4 = tid & 3;
    const int t8 = tid >> 3, q8 = tid & 7;

    uint32_t aD = (uint32_t)__cvta_generic_to_shared(&sd[0][t4][q4 * 4]);
    uint32_t aX = (uint32_t)__cvta_generic_to_shared(&sx[0][t4][q4 * 4]);
    uint32_t aR = (uint32_t)__cvta_generic_to_shared(&sr[0][t4][q4 * 4]);
    uint32_t aP0 = (uint32_t)__cvta_generic_to_shared(&sp[0][t8][q8 * 4]);
    uint32_t aP1 = (uint32_t)__cvta_generic_to_shared(&sp[0][t8 + 32][q8 * 4]);
    const uint32_t bD = sizeof(float) * ST * 16;
    const uint32_t bP = sizeof(float) * ST * 32;

    auto stage = [&](int l0, int buf) {
        cpa16(aD + buf * bD, baseD + (size_t)(l0 + t4) * DM + q4 * 4);
        cpa16(aX + buf * bD, baseX + (size_t)(l0 + t4) * DM + q4 * 4);
        cpa16(aR + buf * bD, baseR + (size_t)(l0 + t4) * DM + q4 * 4);
        cpa16(aP0 + buf * bP, baseP + (size_t)(l0 + t8) * NPROJ + q8 * 4);
        cpa16(aP1 + buf * bP, baseP + (size_t)(l0 + t8 + 32) * NPROJ + q8 * 4);
        cpa_commit();
    };

    stage(0, 0);
    cpa_wait0();
    __syncthreads();

    float h = 0.0f;
    const int NT = L_ / ST;
    for (int tt = 0; tt < NT; ++tt) {
        const int buf = tt & 1;
        if (tt + 1 < NT) stage((tt + 1) * ST, buf ^ 1);

        #pragma unroll 4
        for (int t = 0; t < ST; ++t) {
            const float dlt = sd[buf][t][g];
            const float xv  = sx[buf][t][g];
            const float bv  = sp[buf][t][n];
            const float cv  = sp[buf][t][16 + n];

            const float dA = __expf(dlt * a);
            h = fmaf(dA, h, dlt * bv * xv);

            float py = h * cv;
            py += __shfl_xor_sync(0xffffffffu, py, 8);
            py += __shfl_xor_sync(0xffffffffu, py, 4);
            py += __shfl_xor_sync(0xffffffffu, py, 2);
            py += __shfl_xor_sync(0xffffffffu, py, 1);

            if (n == 0) {
                const float sil = sr[buf][t][g];
                sy[t][g] = __float2half((py + Dd * xv) * sil);
            }
        }
        cpa_wait0();
        __syncthreads();
        if (tid < 128) {
            const int row = tid >> 1, q = tid & 1;
            float4 v = *(float4*)(&sy[row][q * 8]);
            *(float4*)(baseY + (size_t)(tt * ST + row) * DM + q * 8) = v;
        }
        __syncthreads();
    }
}

// ---------------- launch ----------------
extern "C" void kernel_launch(void* const* d_in, const int* in_sizes, int n_in,
                              void* d_out, int out_size)
{
    const float* x_in   = (const float*)d_in[0];
    const float* W_in   = (const float*)d_in[1];
    const float* W_res  = (const float*)d_in[2];
    const float* W_out  = (const float*)d_in[3];
    const float* conv_w = (const float*)d_in[4];
    const float* conv_b = (const float*)d_in[5];
    const float* A_log  = (const float*)d_in[6];
    const float* Dvec   = (const float*)d_in[7];
    const float* W_B    = (const float*)d_in[8];
    const float* W_C    = (const float*)d_in[9];
    const float* W_dt   = (const float*)d_in[10];
    const float* dt_w   = (const float*)d_in[11];
    const float* dt_b   = (const float*)d_in[12];
    float* out = (float*)d_out;

    float  *pres, *pprojp, *pdelta;
    __half *pxh, *pxmh, *pxch, *pprojh, *pyh, *pWir, *pWto, *pWtc, *pWtd;
    cudaGetSymbolAddress((void**)&pres,   g_res);
    cudaGetSymbolAddress((void**)&pprojp, g_projp);
    cudaGetSymbolAddress((void**)&pdelta, g_delta);
    cudaGetSymbolAddress((void**)&pxh,    g_xh);
    cudaGetSymbolAddress((void**)&pxmh,   g_xm_h);
    cudaGetSymbolAddress((void**)&pxch,   g_xch);
    cudaGetSymbolAddress((void**)&pprojh, g_projh);
    cudaGetSymbolAddress((void**)&pyh,    g_yh);
    cudaGetSymbolAddress((void**)&pWir,   g_Wth_inres);
    cudaGetSymbolAddress((void**)&pWto,   g_Wth_out);
    cudaGetSymbolAddress((void**)&pWtc,   g_Wth_cat);
    cudaGetSymbolAddress((void**)&pWtd,   g_Wth_dtw);

    const int smem128 = 3 * (128 * 128 + 128 * 128);   // 98304
    const int smem64  = 3 * (64 * 128 + 128 * 128);    // 73728
    cudaFuncSetAttribute(gemm_h<128, 4>, cudaFuncAttributeMaxDynamicSharedMemorySize, smem128);
    cudaFuncSetAttribute(gemm_h<128, 0>, cudaFuncAttributeMaxDynamicSharedMemorySize, smem128);
    cudaFuncSetAttribute(gemm_h<64, 2>,  cudaFuncAttributeMaxDynamicSharedMemorySize, smem64);
    cudaFuncSetAttribute(gemm_h<64, 0>,  cudaFuncAttributeMaxDynamicSharedMemorySize, smem64);

    // 0: all prep in one kernel
    prep<<<dim3(64, 64, 5), dim3(32, 8)>>>(W_in, W_res, W_out, W_B, W_C, W_dt, dt_w, x_in);

    // 1: fused in+res projection (N=4096): x -> fp16, res -> silu fp32  (512 CTAs)
    gemm_h<128, 4><<<dim3(32, 16), 256, smem128>>>(
        pxh, DIN, pWir, nullptr, pres, pxmh, DM, nullptr, 2 * DM, DIN, 1, 0);

    // 2: conv + silu
    conv_silu_kernel<<<(BL * DM + 255) / 256, 256>>>(conv_w, conv_b);

    // 3: fused skinny projections (N=160), split-K x8 (256 CTAs)
    gemm_h<128, 0><<<dim3(2, 16, KSPLIT), 256, smem128>>>(
        pxch, DM, pWtc, pprojp, nullptr, nullptr, NPROJ, nullptr, NPROJ, DM,
        KSPLIT, (size_t)BL * NPROJ);

    // 4: reduce partials
    proj_reduce<<<(BL * NPROJ + 255) / 256, 256>>>();

    // 5: delta = softplus(dtr @ dt_w + dt_b) (512 CTAs)
    gemm_h<64, 2><<<dim3(16, 32), 256, smem64>>>(
        pprojh + 2 * DS, NPROJ, pWtd, pdelta, nullptr, nullptr, DM, dt_b, DM, DR, 1, 0);

    // 6: selective scan
    scan_kernel<<<B_ * DM / 16, 256>>>(A_log, Dvec);

    // 7: output projection (N=1024) (256 CTAs)
    gemm_h<64, 0><<<dim3(8, 32), 256, smem64>>>(
        pyh, DM, pWto, out, nullptr, nullptr, DIN, nullptr, DIN, DM, 1, 0);
}